// round 12
// baseline (speedup 1.0000x reference)
#include <cuda_runtime.h>

#define NA    32
#define HH    64
#define HS    68      // h/A/B row stride
#define SS    68      // slab row stride (floats)
#define NW    16
#define NPAIR 8
#define NT    512
#define NINV  16
#define NLAY  4
#define OBSW  20

#define SM_H     0
#define SM_A     (SM_H    + NA*HS)
#define SM_B     (SM_A    + NA*HS)
#define SM_MAGG  (SM_B    + NA*HS)
#define SM_EA    (SM_MAGG + NA*HH)
#define SM_W2H   (SM_EA   + NA*NA)        // We2 hi plane, fragment-major (4096 floats)
#define SM_W2L   (SM_W2H  + 4096)         // We2 lo plane
#define SM_WCH   (SM_W2L  + 4096)         // Wc1 hi plane
#define SM_WCL   (SM_WCH  + 4096)         // Wc1 lo plane
#define SM_SLAB  (SM_WCL  + 4096)         // 8 pair-slabs 32x68 (also weight scratch)
#define SM_VEC   (SM_SLAB + NPAIR*NA*SS)
#define SM_LOC   (SM_VEC  + 10*HH)
#define SM_VEL   (SM_LOC  + 2*NA)
#define SM_AGG   (SM_VEL  + 2*NA)
#define SM_CS    (SM_AGG  + 2*NA)         // 16 warps x 32 partials
#define SMEM_FLOATS (SM_CS + NW*NA)
#define SMEM_BYTES  (SMEM_FLOATS * 4)

#define V_W128 0
#define V_W129 1
#define V_BE1  2
#define V_BE2  3
#define V_BC1  4
#define V_WC2  5
#define V_BV1  6
#define V_BN1  7
#define V_BN2  8
#define V_WV2  9

#define PAIRBAR(id) asm volatile("bar.sync %0, 64;" :: "r"(id) : "memory")
#define F4C(v,i) (((const float*)&(v))[i])

__device__ __forceinline__ float siluf(float x) {
    float hx = 0.5f * x;
    float t;
    asm("tanh.approx.f32 %0, %1;" : "=f"(t) : "f"(hx));
    return fmaf(hx, t, hx);
}

__device__ __forceinline__ unsigned rna_u(float x) {
    unsigned u;
    asm("cvt.rna.tf32.f32 %0, %1;" : "=r"(u) : "f"(x));
    return u;
}
__device__ __forceinline__ float rna_f(float x) { return __uint_as_float(rna_u(x)); }

__device__ __forceinline__ void mma8(float &d0, float &d1, float &d2, float &d3,
                                     unsigned a0, unsigned a1, unsigned a2, unsigned a3,
                                     unsigned b0, unsigned b1) {
    asm volatile(
        "mma.sync.aligned.m16n8k8.row.col.f32.tf32.tf32.f32 "
        "{%0,%1,%2,%3},{%4,%5,%6,%7},{%8,%9},{%0,%1,%2,%3};"
        : "+f"(d0), "+f"(d1), "+f"(d2), "+f"(d3)
        : "r"(a0), "r"(a1), "r"(a2), "r"(a3), "r"(b0), "r"(b1));
}

__device__ __forceinline__ float wredsum(float v) {
    v += __shfl_down_sync(0xffffffffu, v, 16);
    v += __shfl_down_sync(0xffffffffu, v, 8);
    v += __shfl_down_sync(0xffffffffu, v, 4);
    v += __shfl_down_sync(0xffffffffu, v, 2);
    v += __shfl_down_sync(0xffffffffu, v, 1);
    return v;
}

// Half GEMM, compensated tf32: D[32e][32n] = slab @ (Whi + Wlo) + bias.
// WH/WL fragment-major: plane[((kt*8+tt)*2+sub)*8+g] = float4 over nt.
// Per kt: 8 scalar a-LDS + 4 LDS.128 weights + 16 HMMA.
__device__ __forceinline__ void mma_gemm_h(const unsigned* __restrict__ slabU,
                                           const float4* __restrict__ WH,
                                           const float4* __restrict__ WL,
                                           const float* __restrict__ bias,
                                           int sub, int g, int t, float (&acc)[2][4][4])
{
    #pragma unroll
    for (int nt = 0; nt < 4; nt++) {
        float2 b = *(const float2*)(bias + nt*8 + 2*t);
        #pragma unroll
        for (int mt = 0; mt < 2; mt++) {
            acc[mt][nt][0] = b.x; acc[mt][nt][1] = b.y;
            acc[mt][nt][2] = b.x; acc[mt][nt][3] = b.y;
        }
    }
    #pragma unroll
    for (int kt = 0; kt < 8; kt++) {
        unsigned a[2][4];
        #pragma unroll
        for (int mt = 0; mt < 2; mt++) {
            const unsigned* base = slabU + (mt*16 + g)*SS + kt*8 + t;
            a[mt][0] = base[0];
            a[mt][1] = base[8*SS];
            a[mt][2] = base[4];
            a[mt][3] = base[8*SS + 4];
        }
        const int idx = ((kt*8 + t)*2 + sub)*8 + g;
        float4 waH = WH[idx], wbH = WH[idx + 64];
        float4 waL = WL[idx], wbL = WL[idx + 64];
        #pragma unroll
        for (int nt = 0; nt < 4; nt++) {
            unsigned b0h = __float_as_uint(F4C(waH, nt));
            unsigned b1h = __float_as_uint(F4C(wbH, nt));
            unsigned b0l = __float_as_uint(F4C(waL, nt));
            unsigned b1l = __float_as_uint(F4C(wbL, nt));
            #pragma unroll
            for (int mt = 0; mt < 2; mt++) {
                mma8(acc[mt][nt][0], acc[mt][nt][1], acc[mt][nt][2], acc[mt][nt][3],
                     a[mt][0], a[mt][1], a[mt][2], a[mt][3], b0h, b1h);
                mma8(acc[mt][nt][0], acc[mt][nt][1], acc[mt][nt][2], acc[mt][nt][3],
                     a[mt][0], a[mt][1], a[mt][2], a[mt][3], b0l, b1l);
            }
        }
    }
}

__global__ void __launch_bounds__(NT, 1)
egnn_kernel(const float* __restrict__ obs,
            const float* __restrict__ scl,
            const float* __restrict__ mn,
            const float* __restrict__ embW,
            const float* __restrict__ embb,
            const float* __restrict__ We1,
            const float* __restrict__ be1,
            const float* __restrict__ We2,
            const float* __restrict__ be2,
            const float* __restrict__ Wc1,
            const float* __restrict__ bc1,
            const float* __restrict__ Wc2,
            const float* __restrict__ bc2,
            const float* __restrict__ Wv1,
            const float* __restrict__ bv1,
            const float* __restrict__ Wv2,
            const float* __restrict__ bv2,
            const float* __restrict__ Wn1,
            const float* __restrict__ bn1,
            const float* __restrict__ Wn2,
            const float* __restrict__ bn2,
            float* __restrict__ out)
{
    extern __shared__ float sm[];
    float* hS    = sm + SM_H;
    float* AS    = sm + SM_A;
    float* BS    = sm + SM_B;
    float* maggS = sm + SM_MAGG;
    float* eaS   = sm + SM_EA;
    float* W2Hs  = sm + SM_W2H;
    float* W2Ls  = sm + SM_W2L;
    float* WCHs  = sm + SM_WCH;
    float* WCLs  = sm + SM_WCL;
    float* slabF = sm + SM_SLAB;
    float* vecS  = sm + SM_VEC;
    float* locS  = sm + SM_LOC;
    float* velS  = sm + SM_VEL;
    float* aggS  = sm + SM_AGG;
    float* csS   = sm + SM_CS;

    float* w128s = vecS + V_W128*HH;
    float* w129s = vecS + V_W129*HH;
    float* be1s  = vecS + V_BE1*HH;
    float* be2s  = vecS + V_BE2*HH;
    float* bc1s  = vecS + V_BC1*HH;
    float* Wc2s  = vecS + V_WC2*HH;
    float* bv1s  = vecS + V_BV1*HH;
    float* bn1s  = vecS + V_BN1*HH;
    float* bn2s  = vecS + V_BN2*HH;
    float* Wv2s  = vecS + V_WV2*HH;

    const int tid  = threadIdx.x;
    const int w    = tid >> 5;         // 0..15
    const int lane = tid & 31;
    const int g    = lane >> 2;        // 0..7
    const int t    = lane & 3;         // 0..3
    const int pair = w >> 1;           // 0..7
    const int sub  = w & 1;            // n-half
    const int bid  = pair + 1;         // named barrier id
    const int gidx = blockIdx.x;

    unsigned* slabU = (unsigned*)(slabF + pair * (NA*SS));
    float* csW = csS + w * NA;

    // ---- stage obs into BS scratch ----
    const float* obsg = obs + (size_t)gidx * NA * OBSW;
    for (int q = tid; q < NA*OBSW; q += NT) BS[q] = obsg[q];
    __syncthreads();

    if (tid < NA*2) {
        int i = tid >> 1, c = tid & 1;
        locS[tid] = BS[i*OBSW + NINV + c];
        velS[tid] = BS[i*OBSW + NINV + 2 + c];
    }
    __syncthreads();

    for (int p = tid; p < NA*NA; p += NT) {
        int i = p >> 5, j = p & 31;
        float dx = locS[i*2+0] - locS[j*2+0];
        float dy = locS[i*2+1] - locS[j*2+1];
        eaS[p] = dx*dx + dy*dy;
    }

    // h = inv @ embW + embb  (warp w: rows 2w, 2w+1)
    {
        float a0[2], a1[2];
        #pragma unroll
        for (int r = 0; r < 2; r++) { a0[r] = embb[lane]; a1[r] = embb[lane+32]; }
        #pragma unroll
        for (int c = 0; c < NINV; c++) {
            float w0 = embW[c*HH + lane];
            float w1 = embW[c*HH + lane + 32];
            #pragma unroll
            for (int r = 0; r < 2; r++) {
                float iv = BS[(w*2+r)*OBSW + c];
                a0[r] += iv*w0; a1[r] += iv*w1;
            }
        }
        #pragma unroll
        for (int r = 0; r < 2; r++) {
            hS[(w*2+r)*HS + lane]      = a0[r];
            hS[(w*2+r)*HS + lane + 32] = a1[r];
        }
    }
    __syncthreads();

    #pragma unroll 1
    for (int l = 0; l < NLAY; l++) {
        // ==== stage edge weights: tf32 (hi,lo) planes, fragment-major ====
        {
            const float4* s2 = (const float4*)(We2 + l*HH*HH);
            const float4* sc = (const float4*)(Wc1 + l*HH*HH);
            for (int t4 = tid; t4 < 1024; t4 += NT) {
                int k  = t4 >> 4, n0 = (t4 & 15) * 4;
                int kt = k >> 3,  tt = k & 7;
                int sb = n0 >> 5, nt = (n0 & 31) >> 3, g0 = n0 & 7;
                int base = (((kt*8 + tt)*2 + sb)*8 + g0)*4 + nt;  // float idx
                float4 w2 = s2[t4], wc = sc[t4];
                float h;
                h = rna_f(w2.x); W2Hs[base+ 0] = h; W2Ls[base+ 0] = rna_f(w2.x - h);
                h = rna_f(w2.y); W2Hs[base+ 4] = h; W2Ls[base+ 4] = rna_f(w2.y - h);
                h = rna_f(w2.z); W2Hs[base+ 8] = h; W2Ls[base+ 8] = rna_f(w2.z - h);
                h = rna_f(w2.w); W2Hs[base+12] = h; W2Ls[base+12] = rna_f(w2.w - h);
                h = rna_f(wc.x); WCHs[base+ 0] = h; WCLs[base+ 0] = rna_f(wc.x - h);
                h = rna_f(wc.y); WCHs[base+ 4] = h; WCLs[base+ 4] = rna_f(wc.y - h);
                h = rna_f(wc.z); WCHs[base+ 8] = h; WCLs[base+ 8] = rna_f(wc.z - h);
                h = rna_f(wc.w); WCHs[base+12] = h; WCLs[base+12] = rna_f(wc.w - h);
            }
            const float4* We1l = (const float4*)(We1 + l*130*HH);
            float4* scr = (float4*)slabF;
            for (int q = tid; q < 2048; q += NT) scr[q] = We1l[q];
            if (tid < HH) {
                w128s[tid] = We1[(l*130 + 128)*HH + tid];
                w129s[tid] = We1[(l*130 + 129)*HH + tid];
                be1s[tid]  = be1[l*HH + tid];
                be2s[tid]  = be2[l*HH + tid];
                bc1s[tid]  = bc1[l*HH + tid];
                Wc2s[tid]  = Wc2[l*HH + tid];
                bv1s[tid]  = bv1[l*HH + tid];
                bn1s[tid]  = bn1[l*HH + tid];
                bn2s[tid]  = bn2[l*HH + tid];
                Wv2s[tid]  = Wv2[l*HH + tid];
            }
        }
        const float bc2l = bc2[l];
        const float bv2l = bv2[l];
        __syncthreads();

        // ==== phase A: A = h@We1A + be1, B = h@We1B (rows 2w, 2w+1) ====
        {
            const float* We1As = slabF;
            const float* We1Bs = slabF + HH*HH;
            float a0[2], a1[2], b0[2], b1[2];
            #pragma unroll
            for (int r = 0; r < 2; r++) {
                a0[r] = be1s[lane]; a1[r] = be1s[lane + 32];
                b0[r] = 0.f; b1[r] = 0.f;
            }
            #pragma unroll 8
            for (int c = 0; c < HH; c++) {
                const float* wrA = We1As + c*HH;
                const float* wrB = We1Bs + c*HH;
                float wa0 = wrA[lane], wa1 = wrA[lane+32];
                float wb0 = wrB[lane], wb1 = wrB[lane+32];
                #pragma unroll
                for (int r = 0; r < 2; r++) {
                    float hv = hS[(w*2+r)*HS + c];
                    a0[r] += hv*wa0; a1[r] += hv*wa1;
                    b0[r] += hv*wb0; b1[r] += hv*wb1;
                }
            }
            #pragma unroll
            for (int r = 0; r < 2; r++) {
                AS[(w*2+r)*HS + lane]      = a0[r];
                AS[(w*2+r)*HS + lane + 32] = a1[r];
                BS[(w*2+r)*HS + lane]      = b0[r];
                BS[(w*2+r)*HS + lane + 32] = b1[r];
            }
        }
        __syncthreads();

        // ==== edge phase: warp pair = one receiver; sub = n-half ====
        #pragma unroll 1
        for (int it = 0; it < 4; it++) {
            const int i = it*NPAIR + pair;

            // -- m1 construction (lane = sender j), this warp's channel half --
            float dnx, dny;
            {
                const int j = lane;
                float dx = locS[i*2+0] - locS[j*2+0];
                float dy = locS[i*2+1] - locS[j*2+1];
                float rad = dx*dx + dy*dy;
                float invr = __fdividef(1.0f, sqrtf(rad) + 1.0f);
                dnx = dx * invr; dny = dy * invr;
                float eav = eaS[i*NA + j];
                const float* Ai = AS + i*HS;
                const float* Bj = BS + j*HS;
                unsigned* srow = slabU + j*SS;
                const int c4lo = sub*8;
                #pragma unroll
                for (int c4i = 0; c4i < 8; c4i++) {
                    int c4 = c4lo + c4i;
                    float4 wA = *(const float4*)(w128s + c4*4);
                    float4 wB = *(const float4*)(w129s + c4*4);
                    float4 a4 = *(const float4*)(Ai + c4*4);
                    float4 b4 = *(const float4*)(Bj + c4*4);
                    uint4 o;
                    o.x = rna_u(siluf(a4.x + b4.x + rad*wA.x + eav*wB.x));
                    o.y = rna_u(siluf(a4.y + b4.y + rad*wA.y + eav*wB.y));
                    o.z = rna_u(siluf(a4.z + b4.z + rad*wA.z + eav*wB.z));
                    o.w = rna_u(siluf(a4.w + b4.w + rad*wA.w + eav*wB.w));
                    *(uint4*)(srow + c4*4) = o;
                }
            }
            PAIRBAR(bid);                       // m1 complete (both halves)

            float acc[2][4][4];

            // -- GEMM1 (tensor): m2-half = silu(m1 @ We2 + be2) --
            mma_gemm_h(slabU, (const float4*)W2Hs, (const float4*)W2Ls,
                       be2s + sub*32, sub, g, t, acc);
            PAIRBAR(bid);                       // both GEMM1 reads done
            {
                float maggL[8];
                #pragma unroll
                for (int s = 0; s < 8; s++) maggL[s] = 0.f;
                float vm[2][2];
                #pragma unroll
                for (int mt = 0; mt < 2; mt++) {
                    int r0 = mt*16 + g;
                    vm[mt][0] = (r0 == i) ? 0.f : 1.f;
                    vm[mt][1] = (r0 + 8 == i) ? 0.f : 1.f;
                }
                #pragma unroll
                for (int mt = 0; mt < 2; mt++) {
                    unsigned* r0p = slabU + (mt*16 + g)*SS + sub*32 + 2*t;
                    unsigned* r1p = r0p + 8*SS;
                    #pragma unroll
                    for (int nt = 0; nt < 4; nt++) {
                        float sv0 = siluf(acc[mt][nt][0]);
                        float sv1 = siluf(acc[mt][nt][1]);
                        float sv2 = siluf(acc[mt][nt][2]);
                        float sv3 = siluf(acc[mt][nt][3]);
                        maggL[nt*2+0] = fmaf(vm[mt][0], sv0, maggL[nt*2+0]);
                        maggL[nt*2+0] = fmaf(vm[mt][1], sv2, maggL[nt*2+0]);
                        maggL[nt*2+1] = fmaf(vm[mt][0], sv1, maggL[nt*2+1]);
                        maggL[nt*2+1] = fmaf(vm[mt][1], sv3, maggL[nt*2+1]);
                        *(uint2*)(r0p + nt*8) = make_uint2(rna_u(sv0), rna_u(sv1));
                        *(uint2*)(r1p + nt*8) = make_uint2(rna_u(sv2), rna_u(sv3));
                    }
                }
                #pragma unroll
                for (int s = 0; s < 8; s++) {
                    maggL[s] += __shfl_xor_sync(0xffffffffu, maggL[s], 4);
                    maggL[s] += __shfl_xor_sync(0xffffffffu, maggL[s], 8);
                    maggL[s] += __shfl_xor_sync(0xffffffffu, maggL[s], 16);
                }
                if (g == 0) {
                    #pragma unroll
                    for (int nt = 0; nt < 4; nt++)
                        *(float2*)(maggS + i*HH + sub*32 + nt*8 + 2*t) =
                            make_float2(maggL[2*nt], maggL[2*nt+1]);
                }
            }
            PAIRBAR(bid);                       // m2 complete (both halves)

            // -- GEMM2 (tensor): t2-half; cs partial = t2.Wc2-half --
            mma_gemm_h(slabU, (const float4*)WCHs, (const float4*)WCLs,
                       bc1s + sub*32, sub, g, t, acc);
            {
                float csL[4] = {0.f, 0.f, 0.f, 0.f};
                #pragma unroll
                for (int nt = 0; nt < 4; nt++) {
                    float2 wc = *(const float2*)(Wc2s + sub*32 + nt*8 + 2*t);
                    #pragma unroll
                    for (int mt = 0; mt < 2; mt++) {
                        csL[mt*2+0] = fmaf(siluf(acc[mt][nt][0]), wc.x, csL[mt*2+0]);
                        csL[mt*2+0] = fmaf(siluf(acc[mt][nt][1]), wc.y, csL[mt*2+0]);
                        csL[mt*2+1] = fmaf(siluf(acc[mt][nt][2]), wc.x, csL[mt*2+1]);
                        csL[mt*2+1] = fmaf(siluf(acc[mt][nt][3]), wc.y, csL[mt*2+1]);
                    }
                }
                #pragma unroll
                for (int q = 0; q < 4; q++) {
                    csL[q] += __shfl_xor_sync(0xffffffffu, csL[q], 1);
                    csL[q] += __shfl_xor_sync(0xffffffffu, csL[q], 2);
                }
                if (t == 0) {
                    csW[g]      = csL[0];
                    csW[g + 8]  = csL[1];
                    csW[g + 16] = csL[2];
                    csW[g + 24] = csL[3];
                }
            }
            PAIRBAR(bid);                       // cs partials + GEMM2 reads done

            // -- combine cs halves + trans aggregation (sub 0 only) --
            if (sub == 0) {
                float cj = csS[w*NA + lane] + csS[(w+1)*NA + lane] + bc2l;
                float tx = wredsum(dnx * cj);
                float ty = wredsum(dny * cj);
                if (lane == 0) { aggS[i*2+0] = tx; aggS[i*2+1] = ty; }
            }
        }
        __syncthreads();

        // ==== restage node weights into slab scratch ====
        {
            const float4* Wv1l = (const float4*)(Wv1 + l*HH*HH);
            const float4* Wn1l = (const float4*)(Wn1 + l*2*HH*HH);
            const float4* Wn2l = (const float4*)(Wn2 + l*HH*HH);
            float4* d = (float4*)slabF;
            for (int q = tid; q < 1024; q += NT) {
                d[q]        = Wv1l[q];
                d[q + 1024] = Wn1l[q];
                d[q + 2048] = Wn1l[q + 1024];
                d[q + 3072] = Wn2l[q];
            }
        }
        __syncthreads();
        const float* Wv1s = slabF;
        const float* Wn1s = slabF + HH*HH;
        const float* Wn2s = slabF + 3*HH*HH;

        // ==== node phase: phi_v, vel/loc update (rows 2w, 2w+1) ====
        {
            float a0[2], a1[2];
            #pragma unroll
            for (int r = 0; r < 2; r++) { a0[r] = bv1s[lane]; a1[r] = bv1s[lane+32]; }
            #pragma unroll 8
            for (int c = 0; c < HH; c++) {
                const float* wr = Wv1s + c*HH;
                float w0 = wr[lane], w1 = wr[lane+32];
                #pragma unroll
                for (int r = 0; r < 2; r++) {
                    float hv = hS[(w*2+r)*HS + c];
                    a0[r] += hv*w0; a1[r] += hv*w1;
                }
            }
            float wv2a = Wv2s[lane], wv2b = Wv2s[lane + 32];
            #pragma unroll
            for (int r = 0; r < 2; r++) {
                float part = wredsum(siluf(a0[r])*wv2a + siluf(a1[r])*wv2b);
                if (lane == 0) {
                    int i = w*2 + r;
                    float phi = part + bv2l;
                    float vx = phi*velS[i*2+0] + aggS[i*2+0]*(1.0f/31.0f);
                    float vy = phi*velS[i*2+1] + aggS[i*2+1]*(1.0f/31.0f);
                    velS[i*2+0] = vx; velS[i*2+1] = vy;
                    locS[i*2+0] += vx; locS[i*2+1] += vy;
                }
            }
        }

        // ==== U = silu([h, magg] @ Wn1 + bn1) -> AS ====
        {
            float a0[2], a1[2];
            #pragma unroll
            for (int r = 0; r < 2; r++) { a0[r] = bn1s[lane]; a1[r] = bn1s[lane+32]; }
            #pragma unroll 8
            for (int c = 0; c < HH; c++) {
                const float* wr = Wn1s + c*HH;
                float w0 = wr[lane], w1 = wr[lane+32];
                #pragma unroll
                for (int r = 0; r < 2; r++) {
                    float hv = hS[(w*2+r)*HS + c];
                    a0[r] += hv*w0; a1[r] += hv*w1;
                }
            }
            #pragma unroll 8
            for (int c = 0; c < HH; c++) {
                const float* wr = Wn1s + (HH + c)*HH;
                float w0 = wr[lane], w1 = wr[lane+32];
                #pragma unroll
                for (int r = 0; r < 2; r++) {
                    float mv = maggS[(w*2+r)*HH + c];
                    a0[r] += mv*w0; a1[r] += mv*w1;
                }
            }
            #pragma unroll
            for (int r = 0; r < 2; r++) {
                AS[(w*2+r)*HS + lane]      = siluf(a0[r]);
                AS[(w*2+r)*HS + lane + 32] = siluf(a1[r]);
            }
        }

        // ==== h += U @ Wn2 + bn2 ====  (warp-local rows)
        {
            float a0[2], a1[2];
            #pragma unroll
            for (int r = 0; r < 2; r++) { a0[r] = bn2s[lane]; a1[r] = bn2s[lane+32]; }
            #pragma unroll 8
            for (int c = 0; c < HH; c++) {
                const float* wr = Wn2s + c*HH;
                float w0 = wr[lane], w1 = wr[lane+32];
                #pragma unroll
                for (int r = 0; r < 2; r++) {
                    float uv = AS[(w*2+r)*HS + c];
                    a0[r] += uv*w0; a1[r] += uv*w1;
                }
            }
            #pragma unroll
            for (int r = 0; r < 2; r++) {
                hS[(w*2+r)*HS + lane]      += a0[r];
                hS[(w*2+r)*HS + lane + 32] += a1[r];
            }
        }
        __syncthreads();
    }

    // ---- output ----
    if (tid < NA*2) {
        int i = tid >> 1, c = tid & 1;
        out[((size_t)gidx*NA + i)*2 + c] = scl[c]*velS[tid] + mn[c];
    }
}

extern "C" void kernel_launch(void* const* d_in, const int* in_sizes, int n_in,
                              void* d_out, int out_size) {
    const float* obs  = (const float*)d_in[0];
    const float* scl  = (const float*)d_in[3];
    const float* mn   = (const float*)d_in[4];
    const float* embW = (const float*)d_in[5];
    const float* embb = (const float*)d_in[6];
    const float* We1  = (const float*)d_in[7];
    const float* be1  = (const float*)d_in[8];
    const float* We2  = (const float*)d_in[9];
    const float* be2  = (const float*)d_in[10];
    const float* Wc1  = (const float*)d_in[11];
    const float* bc1  = (const float*)d_in[12];
    const float* Wc2  = (const float*)d_in[13];
    const float* bc2  = (const float*)d_in[14];
    const float* Wv1  = (const float*)d_in[15];
    const float* bv1  = (const float*)d_in[16];
    const float* Wv2  = (const float*)d_in[17];
    const float* bv2  = (const float*)d_in[18];
    const float* Wn1  = (const float*)d_in[19];
    const float* bn1  = (const float*)d_in[20];
    const float* Wn2  = (const float*)d_in[21];
    const float* bn2  = (const float*)d_in[22];
    float* out = (float*)d_out;

    int n_nodes = in_sizes[0] / OBSW;
    int groups  = n_nodes / NA;

    cudaFuncSetAttribute(egnn_kernel, cudaFuncAttributeMaxDynamicSharedMemorySize, SMEM_BYTES);
    egnn_kernel<<<groups, NT, SMEM_BYTES>>>(
        obs, scl, mn, embW, embb,
        We1, be1, We2, be2, Wc1, bc1, Wc2, bc2,
        Wv1, bv1, Wv2, bv2, Wn1, bn1, Wn2, bn2, out);
}

// round 13
// speedup vs baseline: 1.4516x; 1.4516x over previous
#include <cuda_runtime.h>

#define NA    32
#define HH    64
#define HS    68      // h/A/B row stride
#define SS    68      // slab row stride (floats)
#define WROW  72      // weight plane row stride in floats (18 float4; 18 mod 8 = 2 -> conflict-free)
#define NW    16
#define NPAIR 8
#define NT    512
#define NINV  16
#define NLAY  4
#define OBSW  20

#define SM_H     0
#define SM_A     (SM_H    + NA*HS)
#define SM_B     (SM_A    + NA*HS)
#define SM_MAGG  (SM_B    + NA*HS)
#define SM_EA    (SM_MAGG + NA*HH)
#define SM_W2H   (SM_EA   + NA*NA)        // We2 hi plane, fragment-major padded (64*WROW)
#define SM_W2L   (SM_W2H  + 64*WROW)      // We2 lo plane
#define SM_WCH   (SM_W2L  + 64*WROW)      // Wc1 hi plane
#define SM_WCL   (SM_WCH  + 64*WROW)      // Wc1 lo plane
#define SM_SLAB  (SM_WCL  + 64*WROW)      // 8 pair-slabs 32x68 (also weight scratch)
#define SM_VEC   (SM_SLAB + NPAIR*NA*SS)
#define SM_LOC   (SM_VEC  + 10*HH)
#define SM_VEL   (SM_LOC  + 2*NA)
#define SM_AGG   (SM_VEL  + 2*NA)
#define SM_CS    (SM_AGG  + 2*NA)         // 16 warps x 32 partials
#define SMEM_FLOATS (SM_CS + NW*NA)
#define SMEM_BYTES  (SMEM_FLOATS * 4)

#define V_W128 0
#define V_W129 1
#define V_BE1  2
#define V_BE2  3
#define V_BC1  4
#define V_WC2  5
#define V_BV1  6
#define V_BN1  7
#define V_BN2  8
#define V_WV2  9

#define PAIRBAR(id) asm volatile("bar.sync %0, 64;" :: "r"(id) : "memory")
#define F4C(v,i) (((const float*)&(v))[i])

__device__ __forceinline__ float siluf(float x) {
    float hx = 0.5f * x;
    float t;
    asm("tanh.approx.f32 %0, %1;" : "=f"(t) : "f"(hx));
    return fmaf(hx, t, hx);
}

__device__ __forceinline__ unsigned rna_u(float x) {
    unsigned u;
    asm("cvt.rna.tf32.f32 %0, %1;" : "=r"(u) : "f"(x));
    return u;
}
__device__ __forceinline__ float rna_f(float x) { return __uint_as_float(rna_u(x)); }

__device__ __forceinline__ void mma8(float &d0, float &d1, float &d2, float &d3,
                                     unsigned a0, unsigned a1, unsigned a2, unsigned a3,
                                     unsigned b0, unsigned b1) {
    asm volatile(
        "mma.sync.aligned.m16n8k8.row.col.f32.tf32.tf32.f32 "
        "{%0,%1,%2,%3},{%4,%5,%6,%7},{%8,%9},{%0,%1,%2,%3};"
        : "+f"(d0), "+f"(d1), "+f"(d2), "+f"(d3)
        : "r"(a0), "r"(a1), "r"(a2), "r"(a3), "r"(b0), "r"(b1));
}

__device__ __forceinline__ float wredsum(float v) {
    v += __shfl_down_sync(0xffffffffu, v, 16);
    v += __shfl_down_sync(0xffffffffu, v, 8);
    v += __shfl_down_sync(0xffffffffu, v, 4);
    v += __shfl_down_sync(0xffffffffu, v, 2);
    v += __shfl_down_sync(0xffffffffu, v, 1);
    return v;
}

// Half GEMM, compensated tf32: D[32e][32n] = slab @ (Whi + Wlo) + bias.
// Planes fragment-major, PADDED row stride 18 float4:
//   plane_f4[(k)*18 + sub*8 + g] = float4 over nt, where k = kt*8 + t.
// Per kt: 8 scalar a-LDS (conflict-free) + 4 LDS.128 weights (4 wf each) + 16 HMMA.
__device__ __forceinline__ void mma_gemm_h(const unsigned* __restrict__ slabU,
                                           const float4* __restrict__ WH,
                                           const float4* __restrict__ WL,
                                           const float* __restrict__ bias,
                                           int sub, int g, int t, float (&acc)[2][4][4])
{
    #pragma unroll
    for (int nt = 0; nt < 4; nt++) {
        float2 b = *(const float2*)(bias + nt*8 + 2*t);
        #pragma unroll
        for (int mt = 0; mt < 2; mt++) {
            acc[mt][nt][0] = b.x; acc[mt][nt][1] = b.y;
            acc[mt][nt][2] = b.x; acc[mt][nt][3] = b.y;
        }
    }
    #pragma unroll
    for (int kt = 0; kt < 8; kt++) {
        unsigned a[2][4];
        #pragma unroll
        for (int mt = 0; mt < 2; mt++) {
            const unsigned* base = slabU + (mt*16 + g)*SS + kt*8 + t;
            a[mt][0] = base[0];
            a[mt][1] = base[8*SS];
            a[mt][2] = base[4];
            a[mt][3] = base[8*SS + 4];
        }
        const int idx = (kt*8 + t)*18 + sub*8 + g;   // float4 units
        float4 waH = WH[idx], wbH = WH[idx + 72];    // +4 rows = 4*18 f4
        float4 waL = WL[idx], wbL = WL[idx + 72];
        #pragma unroll
        for (int nt = 0; nt < 4; nt++) {
            unsigned b0h = __float_as_uint(F4C(waH, nt));
            unsigned b1h = __float_as_uint(F4C(wbH, nt));
            unsigned b0l = __float_as_uint(F4C(waL, nt));
            unsigned b1l = __float_as_uint(F4C(wbL, nt));
            #pragma unroll
            for (int mt = 0; mt < 2; mt++) {
                mma8(acc[mt][nt][0], acc[mt][nt][1], acc[mt][nt][2], acc[mt][nt][3],
                     a[mt][0], a[mt][1], a[mt][2], a[mt][3], b0h, b1h);
                mma8(acc[mt][nt][0], acc[mt][nt][1], acc[mt][nt][2], acc[mt][nt][3],
                     a[mt][0], a[mt][1], a[mt][2], a[mt][3], b0l, b1l);
            }
        }
    }
}

__global__ void __launch_bounds__(NT, 1)
egnn_kernel(const float* __restrict__ obs,
            const float* __restrict__ scl,
            const float* __restrict__ mn,
            const float* __restrict__ embW,
            const float* __restrict__ embb,
            const float* __restrict__ We1,
            const float* __restrict__ be1,
            const float* __restrict__ We2,
            const float* __restrict__ be2,
            const float* __restrict__ Wc1,
            const float* __restrict__ bc1,
            const float* __restrict__ Wc2,
            const float* __restrict__ bc2,
            const float* __restrict__ Wv1,
            const float* __restrict__ bv1,
            const float* __restrict__ Wv2,
            const float* __restrict__ bv2,
            const float* __restrict__ Wn1,
            const float* __restrict__ bn1,
            const float* __restrict__ Wn2,
            const float* __restrict__ bn2,
            float* __restrict__ out)
{
    extern __shared__ float sm[];
    float* hS    = sm + SM_H;
    float* AS    = sm + SM_A;
    float* BS    = sm + SM_B;
    float* maggS = sm + SM_MAGG;
    float* eaS   = sm + SM_EA;
    float* W2Hs  = sm + SM_W2H;
    float* W2Ls  = sm + SM_W2L;
    float* WCHs  = sm + SM_WCH;
    float* WCLs  = sm + SM_WCL;
    float* slabF = sm + SM_SLAB;
    float* vecS  = sm + SM_VEC;
    float* locS  = sm + SM_LOC;
    float* velS  = sm + SM_VEL;
    float* aggS  = sm + SM_AGG;
    float* csS   = sm + SM_CS;

    float* w128s = vecS + V_W128*HH;
    float* w129s = vecS + V_W129*HH;
    float* be1s  = vecS + V_BE1*HH;
    float* be2s  = vecS + V_BE2*HH;
    float* bc1s  = vecS + V_BC1*HH;
    float* Wc2s  = vecS + V_WC2*HH;
    float* bv1s  = vecS + V_BV1*HH;
    float* bn1s  = vecS + V_BN1*HH;
    float* bn2s  = vecS + V_BN2*HH;
    float* Wv2s  = vecS + V_WV2*HH;

    const int tid  = threadIdx.x;
    const int w    = tid >> 5;         // 0..15
    const int lane = tid & 31;
    const int g    = lane >> 2;        // 0..7
    const int t    = lane & 3;         // 0..3
    const int pair = w >> 1;           // 0..7
    const int sub  = w & 1;            // n-half
    const int bid  = pair + 1;         // named barrier id
    const int gidx = blockIdx.x;

    unsigned* slabU = (unsigned*)(slabF + pair * (NA*SS));
    float* csW = csS + w * NA;

    // ---- stage obs into BS scratch ----
    const float* obsg = obs + (size_t)gidx * NA * OBSW;
    for (int q = tid; q < NA*OBSW; q += NT) BS[q] = obsg[q];
    __syncthreads();

    if (tid < NA*2) {
        int i = tid >> 1, c = tid & 1;
        locS[tid] = BS[i*OBSW + NINV + c];
        velS[tid] = BS[i*OBSW + NINV + 2 + c];
    }
    __syncthreads();

    for (int p = tid; p < NA*NA; p += NT) {
        int i = p >> 5, j = p & 31;
        float dx = locS[i*2+0] - locS[j*2+0];
        float dy = locS[i*2+1] - locS[j*2+1];
        eaS[p] = dx*dx + dy*dy;
    }

    // h = inv @ embW + embb  (warp w: rows 2w, 2w+1)
    {
        float a0[2], a1[2];
        #pragma unroll
        for (int r = 0; r < 2; r++) { a0[r] = embb[lane]; a1[r] = embb[lane+32]; }
        #pragma unroll
        for (int c = 0; c < NINV; c++) {
            float w0 = embW[c*HH + lane];
            float w1 = embW[c*HH + lane + 32];
            #pragma unroll
            for (int r = 0; r < 2; r++) {
                float iv = BS[(w*2+r)*OBSW + c];
                a0[r] += iv*w0; a1[r] += iv*w1;
            }
        }
        #pragma unroll
        for (int r = 0; r < 2; r++) {
            hS[(w*2+r)*HS + lane]      = a0[r];
            hS[(w*2+r)*HS + lane + 32] = a1[r];
        }
    }
    __syncthreads();

    #pragma unroll 1
    for (int l = 0; l < NLAY; l++) {
        // ==== stage edge weights: tf32 (hi,lo) planes, fragment-major padded ====
        {
            const float4* s2 = (const float4*)(We2 + l*HH*HH);
            const float4* sc = (const float4*)(Wc1 + l*HH*HH);
            for (int t4 = tid; t4 < 1024; t4 += NT) {
                int k  = t4 >> 4, n0 = (t4 & 15) * 4;       // n0 % 8 in {0,4}
                int sb = n0 >> 5, nt = (n0 & 31) >> 3, g0 = n0 & 7;
                int base = k*WROW + (sb*8 + g0)*4 + nt;     // float idx; +4 per n
                float4 w2 = s2[t4], wc = sc[t4];
                float h;
                h = rna_f(w2.x); W2Hs[base+ 0] = h; W2Ls[base+ 0] = rna_f(w2.x - h);
                h = rna_f(w2.y); W2Hs[base+ 4] = h; W2Ls[base+ 4] = rna_f(w2.y - h);
                h = rna_f(w2.z); W2Hs[base+ 8] = h; W2Ls[base+ 8] = rna_f(w2.z - h);
                h = rna_f(w2.w); W2Hs[base+12] = h; W2Ls[base+12] = rna_f(w2.w - h);
                h = rna_f(wc.x); WCHs[base+ 0] = h; WCLs[base+ 0] = rna_f(wc.x - h);
                h = rna_f(wc.y); WCHs[base+ 4] = h; WCLs[base+ 4] = rna_f(wc.y - h);
                h = rna_f(wc.z); WCHs[base+ 8] = h; WCLs[base+ 8] = rna_f(wc.z - h);
                h = rna_f(wc.w); WCHs[base+12] = h; WCLs[base+12] = rna_f(wc.w - h);
            }
            const float4* We1l = (const float4*)(We1 + l*130*HH);
            float4* scr = (float4*)slabF;
            for (int q = tid; q < 2048; q += NT) scr[q] = We1l[q];
            if (tid < HH) {
                w128s[tid] = We1[(l*130 + 128)*HH + tid];
                w129s[tid] = We1[(l*130 + 129)*HH + tid];
                be1s[tid]  = be1[l*HH + tid];
                be2s[tid]  = be2[l*HH + tid];
                bc1s[tid]  = bc1[l*HH + tid];
                Wc2s[tid]  = Wc2[l*HH + tid];
                bv1s[tid]  = bv1[l*HH + tid];
                bn1s[tid]  = bn1[l*HH + tid];
                bn2s[tid]  = bn2[l*HH + tid];
                Wv2s[tid]  = Wv2[l*HH + tid];
            }
        }
        const float bc2l = bc2[l];
        const float bv2l = bv2[l];
        __syncthreads();

        // ==== phase A: A = h@We1A + be1, B = h@We1B (rows 2w, 2w+1) ====
        {
            const float* We1As = slabF;
            const float* We1Bs = slabF + HH*HH;
            float a0[2], a1[2], b0[2], b1[2];
            #pragma unroll
            for (int r = 0; r < 2; r++) {
                a0[r] = be1s[lane]; a1[r] = be1s[lane + 32];
                b0[r] = 0.f; b1[r] = 0.f;
            }
            #pragma unroll 8
            for (int c = 0; c < HH; c++) {
                const float* wrA = We1As + c*HH;
                const float* wrB = We1Bs + c*HH;
                float wa0 = wrA[lane], wa1 = wrA[lane+32];
                float wb0 = wrB[lane], wb1 = wrB[lane+32];
                #pragma unroll
                for (int r = 0; r < 2; r++) {
                    float hv = hS[(w*2+r)*HS + c];
                    a0[r] += hv*wa0; a1[r] += hv*wa1;
                    b0[r] += hv*wb0; b1[r] += hv*wb1;
                }
            }
            #pragma unroll
            for (int r = 0; r < 2; r++) {
                AS[(w*2+r)*HS + lane]      = a0[r];
                AS[(w*2+r)*HS + lane + 32] = a1[r];
                BS[(w*2+r)*HS + lane]      = b0[r];
                BS[(w*2+r)*HS + lane + 32] = b1[r];
            }
        }
        __syncthreads();

        // ==== edge phase: warp pair = one receiver; sub = n-half ====
        #pragma unroll 1
        for (int it = 0; it < 4; it++) {
            const int i = it*NPAIR + pair;

            // -- m1 construction (lane = sender j), this warp's channel half --
            float dnx, dny;
            {
                const int j = lane;
                float dx = locS[i*2+0] - locS[j*2+0];
                float dy = locS[i*2+1] - locS[j*2+1];
                float rad = dx*dx + dy*dy;
                float invr = __fdividef(1.0f, sqrtf(rad) + 1.0f);
                dnx = dx * invr; dny = dy * invr;
                float eav = eaS[i*NA + j];
                const float* Ai = AS + i*HS;
                const float* Bj = BS + j*HS;
                unsigned* srow = slabU + j*SS;
                const int c4lo = sub*8;
                #pragma unroll
                for (int c4i = 0; c4i < 8; c4i++) {
                    int c4 = c4lo + c4i;
                    float4 wA = *(const float4*)(w128s + c4*4);
                    float4 wB = *(const float4*)(w129s + c4*4);
                    float4 a4 = *(const float4*)(Ai + c4*4);
                    float4 b4 = *(const float4*)(Bj + c4*4);
                    uint4 o;
                    o.x = rna_u(siluf(a4.x + b4.x + rad*wA.x + eav*wB.x));
                    o.y = rna_u(siluf(a4.y + b4.y + rad*wA.y + eav*wB.y));
                    o.z = rna_u(siluf(a4.z + b4.z + rad*wA.z + eav*wB.z));
                    o.w = rna_u(siluf(a4.w + b4.w + rad*wA.w + eav*wB.w));
                    *(uint4*)(srow + c4*4) = o;
                }
            }
            PAIRBAR(bid);                       // m1 complete (both halves)

            float acc[2][4][4];

            // -- GEMM1 (tensor): m2-half = silu(m1 @ We2 + be2) --
            mma_gemm_h(slabU, (const float4*)W2Hs, (const float4*)W2Ls,
                       be2s + sub*32, sub, g, t, acc);
            PAIRBAR(bid);                       // both GEMM1 reads done
            {
                float maggL[8];
                #pragma unroll
                for (int s = 0; s < 8; s++) maggL[s] = 0.f;
                float vm[2][2];
                #pragma unroll
                for (int mt = 0; mt < 2; mt++) {
                    int r0 = mt*16 + g;
                    vm[mt][0] = (r0 == i) ? 0.f : 1.f;
                    vm[mt][1] = (r0 + 8 == i) ? 0.f : 1.f;
                }
                #pragma unroll
                for (int mt = 0; mt < 2; mt++) {
                    unsigned* r0p = slabU + (mt*16 + g)*SS + sub*32 + 2*t;
                    unsigned* r1p = r0p + 8*SS;
                    #pragma unroll
                    for (int nt = 0; nt < 4; nt++) {
                        float sv0 = siluf(acc[mt][nt][0]);
                        float sv1 = siluf(acc[mt][nt][1]);
                        float sv2 = siluf(acc[mt][nt][2]);
                        float sv3 = siluf(acc[mt][nt][3]);
                        maggL[nt*2+0] = fmaf(vm[mt][0], sv0, maggL[nt*2+0]);
                        maggL[nt*2+0] = fmaf(vm[mt][1], sv2, maggL[nt*2+0]);
                        maggL[nt*2+1] = fmaf(vm[mt][0], sv1, maggL[nt*2+1]);
                        maggL[nt*2+1] = fmaf(vm[mt][1], sv3, maggL[nt*2+1]);
                        *(uint2*)(r0p + nt*8) = make_uint2(rna_u(sv0), rna_u(sv1));
                        *(uint2*)(r1p + nt*8) = make_uint2(rna_u(sv2), rna_u(sv3));
                    }
                }
                #pragma unroll
                for (int s = 0; s < 8; s++) {
                    maggL[s] += __shfl_xor_sync(0xffffffffu, maggL[s], 4);
                    maggL[s] += __shfl_xor_sync(0xffffffffu, maggL[s], 8);
                    maggL[s] += __shfl_xor_sync(0xffffffffu, maggL[s], 16);
                }
                if (g == 0) {
                    #pragma unroll
                    for (int nt = 0; nt < 4; nt++)
                        *(float2*)(maggS + i*HH + sub*32 + nt*8 + 2*t) =
                            make_float2(maggL[2*nt], maggL[2*nt+1]);
                }
            }
            PAIRBAR(bid);                       // m2 complete (both halves)

            // -- GEMM2 (tensor): t2-half; cs partial = t2.Wc2-half --
            mma_gemm_h(slabU, (const float4*)WCHs, (const float4*)WCLs,
                       bc1s + sub*32, sub, g, t, acc);
            {
                float csL[4] = {0.f, 0.f, 0.f, 0.f};
                #pragma unroll
                for (int nt = 0; nt < 4; nt++) {
                    float2 wc = *(const float2*)(Wc2s + sub*32 + nt*8 + 2*t);
                    #pragma unroll
                    for (int mt = 0; mt < 2; mt++) {
                        csL[mt*2+0] = fmaf(siluf(acc[mt][nt][0]), wc.x, csL[mt*2+0]);
                        csL[mt*2+0] = fmaf(siluf(acc[mt][nt][1]), wc.y, csL[mt*2+0]);
                        csL[mt*2+1] = fmaf(siluf(acc[mt][nt][2]), wc.x, csL[mt*2+1]);
                        csL[mt*2+1] = fmaf(siluf(acc[mt][nt][3]), wc.y, csL[mt*2+1]);
                    }
                }
                #pragma unroll
                for (int q = 0; q < 4; q++) {
                    csL[q] += __shfl_xor_sync(0xffffffffu, csL[q], 1);
                    csL[q] += __shfl_xor_sync(0xffffffffu, csL[q], 2);
                }
                if (t == 0) {
                    csW[g]      = csL[0];
                    csW[g + 8]  = csL[1];
                    csW[g + 16] = csL[2];
                    csW[g + 24] = csL[3];
                }
            }
            PAIRBAR(bid);                       // cs partials + GEMM2 reads done

            // -- combine cs halves + trans aggregation (sub 0 only) --
            if (sub == 0) {
                float cj = csS[w*NA + lane] + csS[(w+1)*NA + lane] + bc2l;
                float tx = wredsum(dnx * cj);
                float ty = wredsum(dny * cj);
                if (lane == 0) { aggS[i*2+0] = tx; aggS[i*2+1] = ty; }
            }
        }
        __syncthreads();

        // ==== restage node weights into slab scratch ====
        {
            const float4* Wv1l = (const float4*)(Wv1 + l*HH*HH);
            const float4* Wn1l = (const float4*)(Wn1 + l*2*HH*HH);
            const float4* Wn2l = (const float4*)(Wn2 + l*HH*HH);
            float4* d = (float4*)slabF;
            for (int q = tid; q < 1024; q += NT) {
                d[q]        = Wv1l[q];
                d[q + 1024] = Wn1l[q];
                d[q + 2048] = Wn1l[q + 1024];
                d[q + 3072] = Wn2l[q];
            }
        }
        __syncthreads();
        const float* Wv1s = slabF;
        const float* Wn1s = slabF + HH*HH;
        const float* Wn2s = slabF + 3*HH*HH;

        // ==== node phase: phi_v, vel/loc update (rows 2w, 2w+1) ====
        {
            float a0[2], a1[2];
            #pragma unroll
            for (int r = 0; r < 2; r++) { a0[r] = bv1s[lane]; a1[r] = bv1s[lane+32]; }
            #pragma unroll 8
            for (int c = 0; c < HH; c++) {
                const float* wr = Wv1s + c*HH;
                float w0 = wr[lane], w1 = wr[lane+32];
                #pragma unroll
                for (int r = 0; r < 2; r++) {
                    float hv = hS[(w*2+r)*HS + c];
                    a0[r] += hv*w0; a1[r] += hv*w1;
                }
            }
            float wv2a = Wv2s[lane], wv2b = Wv2s[lane + 32];
            #pragma unroll
            for (int r = 0; r < 2; r++) {
                float part = wredsum(siluf(a0[r])*wv2a + siluf(a1[r])*wv2b);
                if (lane == 0) {
                    int i = w*2 + r;
                    float phi = part + bv2l;
                    float vx = phi*velS[i*2+0] + aggS[i*2+0]*(1.0f/31.0f);
                    float vy = phi*velS[i*2+1] + aggS[i*2+1]*(1.0f/31.0f);
                    velS[i*2+0] = vx; velS[i*2+1] = vy;
                    locS[i*2+0] += vx; locS[i*2+1] += vy;
                }
            }
        }

        // ==== U = silu([h, magg] @ Wn1 + bn1) -> AS ====
        {
            float a0[2], a1[2];
            #pragma unroll
            for (int r = 0; r < 2; r++) { a0[r] = bn1s[lane]; a1[r] = bn1s[lane+32]; }
            #pragma unroll 8
            for (int c = 0; c < HH; c++) {
                const float* wr = Wn1s + c*HH;
                float w0 = wr[lane], w1 = wr[lane+32];
                #pragma unroll
                for (int r = 0; r < 2; r++) {
                    float hv = hS[(w*2+r)*HS + c];
                    a0[r] += hv*w0; a1[r] += hv*w1;
                }
            }
            #pragma unroll 8
            for (int c = 0; c < HH; c++) {
                const float* wr = Wn1s + (HH + c)*HH;
                float w0 = wr[lane], w1 = wr[lane+32];
                #pragma unroll
                for (int r = 0; r < 2; r++) {
                    float mv = maggS[(w*2+r)*HH + c];
                    a0[r] += mv*w0; a1[r] += mv*w1;
                }
            }
            #pragma unroll
            for (int r = 0; r < 2; r++) {
                AS[(w*2+r)*HS + lane]      = siluf(a0[r]);
                AS[(w*2+r)*HS + lane + 32] = siluf(a1[r]);
            }
        }

        // ==== h += U @ Wn2 + bn2 ====  (warp-local rows)
        {
            float a0[2], a1[2];
            #pragma unroll
            for (int r = 0; r < 2; r++) { a0[r] = bn2s[lane]; a1[r] = bn2s[lane+32]; }
            #pragma unroll 8
            for (int c = 0; c < HH; c++) {
                const float* wr = Wn2s + c*HH;
                float w0 = wr[lane], w1 = wr[lane+32];
                #pragma unroll
                for (int r = 0; r < 2; r++) {
                    float uv = AS[(w*2+r)*HS + c];
                    a0[r] += uv*w0; a1[r] += uv*w1;
                }
            }
            #pragma unroll
            for (int r = 0; r < 2; r++) {
                hS[(w*2+r)*HS + lane]      += a0[r];
                hS[(w*2+r)*HS + lane + 32] += a1[r];
            }
        }
        __syncthreads();
    }

    // ---- output ----
    if (tid < NA*2) {
        int i = tid >> 1, c = tid & 1;
        out[((size_t)gidx*NA + i)*2 + c] = scl[c]*velS[tid] + mn[c];
    }
}

extern "C" void kernel_launch(void* const* d_in, const int* in_sizes, int n_in,
                              void* d_out, int out_size) {
    const float* obs  = (const float*)d_in[0];
    const float* scl  = (const float*)d_in[3];
    const float* mn   = (const float*)d_in[4];
    const float* embW = (const float*)d_in[5];
    const float* embb = (const float*)d_in[6];
    const float* We1  = (const float*)d_in[7];
    const float* be1  = (const float*)d_in[8];
    const float* We2  = (const float*)d_in[9];
    const float* be2  = (const float*)d_in[10];
    const float* Wc1  = (const float*)d_in[11];
    const float* bc1  = (const float*)d_in[12];
    const float* Wc2  = (const float*)d_in[13];
    const float* bc2  = (const float*)d_in[14];
    const float* Wv1  = (const float*)d_in[15];
    const float* bv1  = (const float*)d_in[16];
    const float* Wv2  = (const float*)d_in[17];
    const float* bv2  = (const float*)d_in[18];
    const float* Wn1  = (const float*)d_in[19];
    const float* bn1  = (const float*)d_in[20];
    const float* Wn2  = (const float*)d_in[21];
    const float* bn2  = (const float*)d_in[22];
    float* out = (float*)d_out;

    int n_nodes = in_sizes[0] / OBSW;
    int groups  = n_nodes / NA;

    cudaFuncSetAttribute(egnn_kernel, cudaFuncAttributeMaxDynamicSharedMemorySize, SMEM_BYTES);
    egnn_kernel<<<groups, NT, SMEM_BYTES>>>(
        obs, scl, mn, embW, embb,
        We1, be1, We2, be2, Wc1, bc1, Wc2, bc2,
        Wv1, bv1, Wv2, bv2, Wn1, bn1, Wn2, bn2, out);
}

// round 14
// speedup vs baseline: 1.4810x; 1.0203x over previous
#include <cuda_runtime.h>

#define NA    32
#define HH    64
#define HS    68      // h/A/B row stride
#define SS    68      // slab row stride (floats)
#define WROW  72      // weight plane row stride (18 float4; conflict-free)
#define PS    66      // paired node-weight row stride (floats)
#define NW    16
#define NPAIR 8
#define NT    512
#define NINV  16
#define NLAY  4
#define OBSW  20

#define SM_H     0
#define SM_A     (SM_H    + NA*HS)
#define SM_B     (SM_A    + NA*HS)
#define SM_MAGG  (SM_B    + NA*HS)
#define SM_EA    (SM_MAGG + NA*HH)
#define SM_W2H   (SM_EA   + NA*NA)
#define SM_W2L   (SM_W2H  + 64*WROW)
#define SM_WCH   (SM_W2L  + 64*WROW)
#define SM_WCL   (SM_WCH  + 64*WROW)
#define SM_SLAB  (SM_WCL  + 64*WROW)      // 8 pair-slabs 32x68; also paired weight scratch
#define SM_VEC   (SM_SLAB + NPAIR*NA*SS)
#define SM_LOC   (SM_VEC  + 10*HH)
#define SM_VEL   (SM_LOC  + 2*NA)
#define SM_AGG   (SM_VEL  + 2*NA)
#define SM_CS    (SM_AGG  + 2*NA)
#define SMEM_FLOATS (SM_CS + NW*NA)
#define SMEM_BYTES  (SMEM_FLOATS * 4)

// paired-plane offsets inside slab scratch (17408 floats available)
#define NV1   (64*PS)    // 4224
#define NN1   (128*PS)   // 8448

#define V_W128 0
#define V_W129 1
#define V_BE1  2
#define V_BE2  3
#define V_BC1  4
#define V_WC2  5
#define V_BV1  6
#define V_BN1  7
#define V_BN2  8
#define V_WV2  9

#define PAIRBAR(id) asm volatile("bar.sync %0, 64;" :: "r"(id) : "memory")
#define F4C(v,i) (((const float*)&(v))[i])

typedef unsigned long long ull;

__device__ __forceinline__ float siluf(float x) {
    float hx = 0.5f * x;
    float t;
    asm("tanh.approx.f32 %0, %1;" : "=f"(t) : "f"(hx));
    return fmaf(hx, t, hx);
}

__device__ __forceinline__ unsigned rna_u(float x) {
    unsigned u;
    asm("cvt.rna.tf32.f32 %0, %1;" : "=r"(u) : "f"(x));
    return u;
}
__device__ __forceinline__ float rna_f(float x) { return __uint_as_float(rna_u(x)); }

__device__ __forceinline__ ull packf2(float x) {
    unsigned u = __float_as_uint(x);
    ull r;
    asm("mov.b64 %0, {%1, %1};" : "=l"(r) : "r"(u));
    return r;
}
__device__ __forceinline__ ull pack2(float x, float y) {
    ull r;
    asm("mov.b64 %0, {%1, %2};" : "=l"(r) : "r"(__float_as_uint(x)), "r"(__float_as_uint(y)));
    return r;
}
__device__ __forceinline__ void fma2(ull &d, ull a, ull b) {
    asm("fma.rn.f32x2 %0, %1, %2, %0;" : "+l"(d) : "l"(a), "l"(b));
}
__device__ __forceinline__ float2 unpackf2(ull v) {
    unsigned lo, hi;
    asm("mov.b64 {%0, %1}, %2;" : "=r"(lo), "=r"(hi) : "l"(v));
    return make_float2(__uint_as_float(lo), __uint_as_float(hi));
}

__device__ __forceinline__ void mma8(float &d0, float &d1, float &d2, float &d3,
                                     unsigned a0, unsigned a1, unsigned a2, unsigned a3,
                                     unsigned b0, unsigned b1) {
    asm volatile(
        "mma.sync.aligned.m16n8k8.row.col.f32.tf32.tf32.f32 "
        "{%0,%1,%2,%3},{%4,%5,%6,%7},{%8,%9},{%0,%1,%2,%3};"
        : "+f"(d0), "+f"(d1), "+f"(d2), "+f"(d3)
        : "r"(a0), "r"(a1), "r"(a2), "r"(a3), "r"(b0), "r"(b1));
}

__device__ __forceinline__ float wredsum(float v) {
    v += __shfl_down_sync(0xffffffffu, v, 16);
    v += __shfl_down_sync(0xffffffffu, v, 8);
    v += __shfl_down_sync(0xffffffffu, v, 4);
    v += __shfl_down_sync(0xffffffffu, v, 2);
    v += __shfl_down_sync(0xffffffffu, v, 1);
    return v;
}

// Half GEMM, compensated tf32. Planes padded fragment-major (WROW).
// hi/lo grouped per kt: 8 hi HMMAs then 8 lo HMMAs (breaks acc RAW chains).
__device__ __forceinline__ void mma_gemm_h(const unsigned* __restrict__ slabU,
                                           const float4* __restrict__ WH,
                                           const float4* __restrict__ WL,
                                           const float* __restrict__ bias,
                                           int sub, int g, int t, float (&acc)[2][4][4])
{
    #pragma unroll
    for (int nt = 0; nt < 4; nt++) {
        float2 b = *(const float2*)(bias + nt*8 + 2*t);
        #pragma unroll
        for (int mt = 0; mt < 2; mt++) {
            acc[mt][nt][0] = b.x; acc[mt][nt][1] = b.y;
            acc[mt][nt][2] = b.x; acc[mt][nt][3] = b.y;
        }
    }
    #pragma unroll
    for (int kt = 0; kt < 8; kt++) {
        unsigned a[2][4];
        #pragma unroll
        for (int mt = 0; mt < 2; mt++) {
            const unsigned* base = slabU + (mt*16 + g)*SS + kt*8 + t;
            a[mt][0] = base[0];
            a[mt][1] = base[8*SS];
            a[mt][2] = base[4];
            a[mt][3] = base[8*SS + 4];
        }
        const int idx = (kt*8 + t)*18 + sub*8 + g;   // float4 units
        float4 waH = WH[idx], wbH = WH[idx + 72];
        float4 waL = WL[idx], wbL = WL[idx + 72];
        // hi pass
        #pragma unroll
        for (int nt = 0; nt < 4; nt++) {
            unsigned b0h = __float_as_uint(F4C(waH, nt));
            unsigned b1h = __float_as_uint(F4C(wbH, nt));
            mma8(acc[0][nt][0], acc[0][nt][1], acc[0][nt][2], acc[0][nt][3],
                 a[0][0], a[0][1], a[0][2], a[0][3], b0h, b1h);
            mma8(acc[1][nt][0], acc[1][nt][1], acc[1][nt][2], acc[1][nt][3],
                 a[1][0], a[1][1], a[1][2], a[1][3], b0h, b1h);
        }
        // lo pass
        #pragma unroll
        for (int nt = 0; nt < 4; nt++) {
            unsigned b0l = __float_as_uint(F4C(waL, nt));
            unsigned b1l = __float_as_uint(F4C(wbL, nt));
            mma8(acc[0][nt][0], acc[0][nt][1], acc[0][nt][2], acc[0][nt][3],
                 a[0][0], a[0][1], a[0][2], a[0][3], b0l, b1l);
            mma8(acc[1][nt][0], acc[1][nt][1], acc[1][nt][2], acc[1][nt][3],
                 a[1][0], a[1][1], a[1][2], a[1][3], b0l, b1l);
        }
    }
}

__global__ void __launch_bounds__(NT, 1)
egnn_kernel(const float* __restrict__ obs,
            const float* __restrict__ scl,
            const float* __restrict__ mn,
            const float* __restrict__ embW,
            const float* __restrict__ embb,
            const float* __restrict__ We1,
            const float* __restrict__ be1,
            const float* __restrict__ We2,
            const float* __restrict__ be2,
            const float* __restrict__ Wc1,
            const float* __restrict__ bc1,
            const float* __restrict__ Wc2,
            const float* __restrict__ bc2,
            const float* __restrict__ Wv1,
            const float* __restrict__ bv1,
            const float* __restrict__ Wv2,
            const float* __restrict__ bv2,
            const float* __restrict__ Wn1,
            const float* __restrict__ bn1,
            const float* __restrict__ Wn2,
            const float* __restrict__ bn2,
            float* __restrict__ out)
{
    extern __shared__ float sm[];
    float* hS    = sm + SM_H;
    float* AS    = sm + SM_A;
    float* BS    = sm + SM_B;
    float* maggS = sm + SM_MAGG;
    float* eaS   = sm + SM_EA;
    float* W2Hs  = sm + SM_W2H;
    float* W2Ls  = sm + SM_W2L;
    float* WCHs  = sm + SM_WCH;
    float* WCLs  = sm + SM_WCL;
    float* slabF = sm + SM_SLAB;
    float* vecS  = sm + SM_VEC;
    float* locS  = sm + SM_LOC;
    float* velS  = sm + SM_VEL;
    float* aggS  = sm + SM_AGG;
    float* csS   = sm + SM_CS;

    float* w128s = vecS + V_W128*HH;
    float* w129s = vecS + V_W129*HH;
    float* be1s  = vecS + V_BE1*HH;
    float* be2s  = vecS + V_BE2*HH;
    float* bc1s  = vecS + V_BC1*HH;
    float* Wc2s  = vecS + V_WC2*HH;
    float* bv1s  = vecS + V_BV1*HH;
    float* bn1s  = vecS + V_BN1*HH;
    float* bn2s  = vecS + V_BN2*HH;
    float* Wv2s  = vecS + V_WV2*HH;

    const int tid  = threadIdx.x;
    const int w    = tid >> 5;
    const int lane = tid & 31;
    const int g    = lane >> 2;
    const int t    = lane & 3;
    const int pair = w >> 1;
    const int sub  = w & 1;
    const int bid  = pair + 1;
    const int gidx = blockIdx.x;

    unsigned* slabU = (unsigned*)(slabF + pair * (NA*SS));
    float* csW = csS + w * NA;

    // ---- stage obs into BS scratch ----
    const float* obsg = obs + (size_t)gidx * NA * OBSW;
    for (int q = tid; q < NA*OBSW; q += NT) BS[q] = obsg[q];
    __syncthreads();

    if (tid < NA*2) {
        int i = tid >> 1, c = tid & 1;
        locS[tid] = BS[i*OBSW + NINV + c];
        velS[tid] = BS[i*OBSW + NINV + 2 + c];
    }
    __syncthreads();

    for (int p = tid; p < NA*NA; p += NT) {
        int i = p >> 5, j = p & 31;
        float dx = locS[i*2+0] - locS[j*2+0];
        float dy = locS[i*2+1] - locS[j*2+1];
        eaS[p] = dx*dx + dy*dy;
    }

    // h = inv @ embW + embb  (warp w: rows 2w, 2w+1)
    {
        float a0[2], a1[2];
        #pragma unroll
        for (int r = 0; r < 2; r++) { a0[r] = embb[lane]; a1[r] = embb[lane+32]; }
        #pragma unroll
        for (int c = 0; c < NINV; c++) {
            float w0 = embW[c*HH + lane];
            float w1 = embW[c*HH + lane + 32];
            #pragma unroll
            for (int r = 0; r < 2; r++) {
                float iv = BS[(w*2+r)*OBSW + c];
                a0[r] += iv*w0; a1[r] += iv*w1;
            }
        }
        #pragma unroll
        for (int r = 0; r < 2; r++) {
            hS[(w*2+r)*HS + lane]      = a0[r];
            hS[(w*2+r)*HS + lane + 32] = a1[r];
        }
    }
    __syncthreads();

    #pragma unroll 1
    for (int l = 0; l < NLAY; l++) {
        // ==== stage edge weights (tf32 hi/lo padded planes) + paired We1 + vectors ====
        {
            const float4* s2 = (const float4*)(We2 + l*HH*HH);
            const float4* sc = (const float4*)(Wc1 + l*HH*HH);
            for (int t4 = tid; t4 < 1024; t4 += NT) {
                int k  = t4 >> 4, n0 = (t4 & 15) * 4;
                int sb = n0 >> 5, nt = (n0 & 31) >> 3, g0 = n0 & 7;
                int base = k*WROW + (sb*8 + g0)*4 + nt;
                float4 w2 = s2[t4], wc = sc[t4];
                float h;
                h = rna_f(w2.x); W2Hs[base+ 0] = h; W2Ls[base+ 0] = rna_f(w2.x - h);
                h = rna_f(w2.y); W2Hs[base+ 4] = h; W2Ls[base+ 4] = rna_f(w2.y - h);
                h = rna_f(w2.z); W2Hs[base+ 8] = h; W2Ls[base+ 8] = rna_f(w2.z - h);
                h = rna_f(w2.w); W2Hs[base+12] = h; W2Ls[base+12] = rna_f(w2.w - h);
                h = rna_f(wc.x); WCHs[base+ 0] = h; WCLs[base+ 0] = rna_f(wc.x - h);
                h = rna_f(wc.y); WCHs[base+ 4] = h; WCLs[base+ 4] = rna_f(wc.y - h);
                h = rna_f(wc.z); WCHs[base+ 8] = h; WCLs[base+ 8] = rna_f(wc.z - h);
                h = rna_f(wc.w); WCHs[base+12] = h; WCLs[base+12] = rna_f(wc.w - h);
            }
            // We1 rows 0..127 -> paired layout: We1Ap (64xPS), We1Bp (64xPS)
            const float4* We1l = (const float4*)(We1 + l*130*HH);
            for (int q = tid; q < 2048; q += NT) {
                int c = q >> 4, n0 = (q & 15) * 4;
                float4 v = We1l[q];
                float* d = slabF + (c >> 6)*NV1 + (c & 63)*PS + 2*(n0 & 31) + (n0 >> 5);
                d[0] = v.x; d[2] = v.y; d[4] = v.z; d[6] = v.w;
            }
            if (tid < HH) {
                w128s[tid] = We1[(l*130 + 128)*HH + tid];
                w129s[tid] = We1[(l*130 + 129)*HH + tid];
                be1s[tid]  = be1[l*HH + tid];
                be2s[tid]  = be2[l*HH + tid];
                bc1s[tid]  = bc1[l*HH + tid];
                Wc2s[tid]  = Wc2[l*HH + tid];
                bv1s[tid]  = bv1[l*HH + tid];
                bn1s[tid]  = bn1[l*HH + tid];
                bn2s[tid]  = bn2[l*HH + tid];
                Wv2s[tid]  = Wv2[l*HH + tid];
            }
        }
        const float bc2l = bc2[l];
        const float bv2l = bv2[l];
        __syncthreads();

        // ==== phase A (packed): A = h@We1A + be1, B = h@We1B ====
        {
            const float* We1Ap = slabF;
            const float* We1Bp = slabF + NV1;
            ull aA[2], aB[2];
            #pragma unroll
            for (int r = 0; r < 2; r++) {
                aA[r] = pack2(be1s[lane], be1s[lane + 32]);
                aB[r] = 0ull;
            }
            #pragma unroll 8
            for (int c = 0; c < HH; c++) {
                ull wpa = *(const ull*)(We1Ap + c*PS + 2*lane);
                ull wpb = *(const ull*)(We1Bp + c*PS + 2*lane);
                #pragma unroll
                for (int r = 0; r < 2; r++) {
                    ull h2 = packf2(hS[(w*2+r)*HS + c]);
                    fma2(aA[r], h2, wpa);
                    fma2(aB[r], h2, wpb);
                }
            }
            #pragma unroll
            for (int r = 0; r < 2; r++) {
                float2 fa = unpackf2(aA[r]);
                float2 fb = unpackf2(aB[r]);
                AS[(w*2+r)*HS + lane]      = fa.x;
                AS[(w*2+r)*HS + lane + 32] = fa.y;
                BS[(w*2+r)*HS + lane]      = fb.x;
                BS[(w*2+r)*HS + lane + 32] = fb.y;
            }
        }
        __syncthreads();

        // ==== edge phase: warp pair = one receiver; sub = n-half ====
        #pragma unroll 1
        for (int it = 0; it < 4; it++) {
            const int i = it*NPAIR + pair;

            // -- m1 construction (lane = sender j), this warp's channel half --
            float dnx, dny;
            {
                const int j = lane;
                float dx = locS[i*2+0] - locS[j*2+0];
                float dy = locS[i*2+1] - locS[j*2+1];
                float rad = dx*dx + dy*dy;
                float invr = __fdividef(1.0f, sqrtf(rad) + 1.0f);
                dnx = dx * invr; dny = dy * invr;
                float eav = eaS[i*NA + j];
                const float* Ai = AS + i*HS;
                const float* Bj = BS + j*HS;
                unsigned* srow = slabU + j*SS;
                const int c4lo = sub*8;
                #pragma unroll
                for (int c4i = 0; c4i < 8; c4i++) {
                    int c4 = c4lo + c4i;
                    float4 wA = *(const float4*)(w128s + c4*4);
                    float4 wB = *(const float4*)(w129s + c4*4);
                    float4 a4 = *(const float4*)(Ai + c4*4);
                    float4 b4 = *(const float4*)(Bj + c4*4);
                    uint4 o;
                    o.x = rna_u(siluf(a4.x + b4.x + rad*wA.x + eav*wB.x));
                    o.y = rna_u(siluf(a4.y + b4.y + rad*wA.y + eav*wB.y));
                    o.z = rna_u(siluf(a4.z + b4.z + rad*wA.z + eav*wB.z));
                    o.w = rna_u(siluf(a4.w + b4.w + rad*wA.w + eav*wB.w));
                    *(uint4*)(srow + c4*4) = o;
                }
            }
            PAIRBAR(bid);                       // m1 complete (both halves)

            float acc[2][4][4];

            // -- GEMM1 (tensor): m2-half = silu(m1 @ We2 + be2) --
            mma_gemm_h(slabU, (const float4*)W2Hs, (const float4*)W2Ls,
                       be2s + sub*32, sub, g, t, acc);
            PAIRBAR(bid);                       // both GEMM1 reads done
            {
                float maggL[8];
                #pragma unroll
                for (int s = 0; s < 8; s++) maggL[s] = 0.f;
                float vm[2][2];
                #pragma unroll
                for (int mt = 0; mt < 2; mt++) {
                    int r0 = mt*16 + g;
                    vm[mt][0] = (r0 == i) ? 0.f : 1.f;
                    vm[mt][1] = (r0 + 8 == i) ? 0.f : 1.f;
                }
                #pragma unroll
                for (int mt = 0; mt < 2; mt++) {
                    unsigned* r0p = slabU + (mt*16 + g)*SS + sub*32 + 2*t;
                    unsigned* r1p = r0p + 8*SS;
                    #pragma unroll
                    for (int nt = 0; nt < 4; nt++) {
                        float sv0 = siluf(acc[mt][nt][0]);
                        float sv1 = siluf(acc[mt][nt][1]);
                        float sv2 = siluf(acc[mt][nt][2]);
                        float sv3 = siluf(acc[mt][nt][3]);
                        maggL[nt*2+0] = fmaf(vm[mt][0], sv0, maggL[nt*2+0]);
                        maggL[nt*2+0] = fmaf(vm[mt][1], sv2, maggL[nt*2+0]);
                        maggL[nt*2+1] = fmaf(vm[mt][0], sv1, maggL[nt*2+1]);
                        maggL[nt*2+1] = fmaf(vm[mt][1], sv3, maggL[nt*2+1]);
                        // RZ truncation: HW mma consumes upper tf32 bits of raw f32
                        *(uint2*)(r0p + nt*8) = make_uint2(__float_as_uint(sv0), __float_as_uint(sv1));
                        *(uint2*)(r1p + nt*8) = make_uint2(__float_as_uint(sv2), __float_as_uint(sv3));
                    }
                }
                #pragma unroll
                for (int s = 0; s < 8; s++) {
                    maggL[s] += __shfl_xor_sync(0xffffffffu, maggL[s], 4);
                    maggL[s] += __shfl_xor_sync(0xffffffffu, maggL[s], 8);
                    maggL[s] += __shfl_xor_sync(0xffffffffu, maggL[s], 16);
                }
                if (g == 0) {
                    #pragma unroll
                    for (int nt = 0; nt < 4; nt++)
                        *(float2*)(maggS + i*HH + sub*32 + nt*8 + 2*t) =
                            make_float2(maggL[2*nt], maggL[2*nt+1]);
                }
            }
            PAIRBAR(bid);                       // m2 complete (both halves)

            // -- GEMM2 (tensor): t2-half; cs partial = t2.Wc2-half --
            mma_gemm_h(slabU, (const float4*)WCHs, (const float4*)WCLs,
                       bc1s + sub*32, sub, g, t, acc);
            {
                float csL[4] = {0.f, 0.f, 0.f, 0.f};
                #pragma unroll
                for (int nt = 0; nt < 4; nt++) {
                    float2 wc = *(const float2*)(Wc2s + sub*32 + nt*8 + 2*t);
                    #pragma unroll
                    for (int mt = 0; mt < 2; mt++) {
                        csL[mt*2+0] = fmaf(siluf(acc[mt][nt][0]), wc.x, csL[mt*2+0]);
                        csL[mt*2+0] = fmaf(siluf(acc[mt][nt][1]), wc.y, csL[mt*2+0]);
                        csL[mt*2+1] = fmaf(siluf(acc[mt][nt][2]), wc.x, csL[mt*2+1]);
                        csL[mt*2+1] = fmaf(siluf(acc[mt][nt][3]), wc.y, csL[mt*2+1]);
                    }
                }
                #pragma unroll
                for (int q = 0; q < 4; q++) {
                    csL[q] += __shfl_xor_sync(0xffffffffu, csL[q], 1);
                    csL[q] += __shfl_xor_sync(0xffffffffu, csL[q], 2);
                }
                if (t == 0) {
                    csW[g]      = csL[0];
                    csW[g + 8]  = csL[1];
                    csW[g + 16] = csL[2];
                    csW[g + 24] = csL[3];
                }
            }
            PAIRBAR(bid);                       // cs partials + GEMM2 reads done

            // -- combine cs halves + trans aggregation (sub 0 only) --
            if (sub == 0) {
                float cj = csS[w*NA + lane] + csS[(w+1)*NA + lane] + bc2l;
                float tx = wredsum(dnx * cj);
                float ty = wredsum(dny * cj);
                if (lane == 0) { aggS[i*2+0] = tx; aggS[i*2+1] = ty; }
            }
        }
        __syncthreads();

        // ==== restage node weights (paired layout) into slab scratch ====
        {
            const float4* Wv1l = (const float4*)(Wv1 + l*HH*HH);
            const float4* Wn1l = (const float4*)(Wn1 + l*2*HH*HH);
            const float4* Wn2l = (const float4*)(Wn2 + l*HH*HH);
            for (int q = tid; q < 1024; q += NT) {
                int c = q >> 4, n0 = (q & 15) * 4;
                int off = c*PS + 2*(n0 & 31) + (n0 >> 5);
                float4 a = Wv1l[q];
                float* d1 = slabF + off;
                d1[0] = a.x; d1[2] = a.y; d1[4] = a.z; d1[6] = a.w;
                float4 b = Wn2l[q];
                float* d3 = slabF + NV1 + NN1 + off;
                d3[0] = b.x; d3[2] = b.y; d3[4] = b.z; d3[6] = b.w;
            }
            for (int q = tid; q < 2048; q += NT) {
                int c = q >> 4, n0 = (q & 15) * 4;
                float4 a = Wn1l[q];
                float* d2 = slabF + NV1 + c*PS + 2*(n0 & 31) + (n0 >> 5);
                d2[0] = a.x; d2[2] = a.y; d2[4] = a.z; d2[6] = a.w;
            }
        }
        __syncthreads();
        const float* Wv1p = slabF;
        const float* Wn1p = slabF + NV1;
        const float* Wn2p = slabF + NV1 + NN1;

        // ==== node phase (packed): phi_v, vel/loc update ====
        {
            ull acc2[2];
            #pragma unroll
            for (int r = 0; r < 2; r++) acc2[r] = pack2(bv1s[lane], bv1s[lane+32]);
            #pragma unroll 8
            for (int c = 0; c < HH; c++) {
                ull wp = *(const ull*)(Wv1p + c*PS + 2*lane);
                #pragma unroll
                for (int r = 0; r < 2; r++)
                    fma2(acc2[r], packf2(hS[(w*2+r)*HS + c]), wp);
            }
            float wv2a = Wv2s[lane], wv2b = Wv2s[lane + 32];
            #pragma unroll
            for (int r = 0; r < 2; r++) {
                float2 f = unpackf2(acc2[r]);
                float part = wredsum(siluf(f.x)*wv2a + siluf(f.y)*wv2b);
                if (lane == 0) {
                    int i = w*2 + r;
                    float phi = part + bv2l;
                    float vx = phi*velS[i*2+0] + aggS[i*2+0]*(1.0f/31.0f);
                    float vy = phi*velS[i*2+1] + aggS[i*2+1]*(1.0f/31.0f);
                    velS[i*2+0] = vx; velS[i*2+1] = vy;
                    locS[i*2+0] += vx; locS[i*2+1] += vy;
                }
            }
        }

        // ==== U = silu([h, magg] @ Wn1 + bn1) -> AS (packed) ====
        {
            ull acc2[2];
            #pragma unroll
            for (int r = 0; r < 2; r++) acc2[r] = pack2(bn1s[lane], bn1s[lane+32]);
            #pragma unroll 8
            for (int c = 0; c < HH; c++) {
                ull wp = *(const ull*)(Wn1p + c*PS + 2*lane);
                #pragma unroll
                for (int r = 0; r < 2; r++)
                    fma2(acc2[r], packf2(hS[(w*2+r)*HS + c]), wp);
            }
            #pragma unroll 8
            for (int c = 0; c < HH; c++) {
                ull wp = *(const ull*)(Wn1p + (HH + c)*PS + 2*lane);
                #pragma unroll
                for (int r = 0; r < 2; r++)
                    fma2(acc2[r], packf2(maggS[(w*2+r)*HH + c]), wp);
            }
            #pragma unroll
            for (int r = 0; r < 2; r++) {
                float2 f = unpackf2(acc2[r]);
                AS[(w*2+r)*HS + lane]      = siluf(f.x);
                AS[(w*2+r)*HS + lane + 32] = siluf(f.y);
            }
        }

        // ==== h += U @ Wn2 + bn2 (packed) ====
        {
            ull acc2[2];
            #pragma unroll
            for (int r = 0; r < 2; r++) acc2[r] = pack2(bn2s[lane], bn2s[lane+32]);
            #pragma unroll 8
            for (int c = 0; c < HH; c++) {
                ull wp = *(const ull*)(Wn2p + c*PS + 2*lane);
                #pragma unroll
                for (int r = 0; r < 2; r++)
                    fma2(acc2[r], packf2(AS[(w*2+r)*HS + c]), wp);
            }
            #pragma unroll
            for (int r = 0; r < 2; r++) {
                float2 f = unpackf2(acc2[r]);
                hS[(w*2+r)*HS + lane]      += f.x;
                hS[(w*2+r)*HS + lane + 32] += f.y;
            }
        }
        __syncthreads();
    }

    // ---- output ----
    if (tid < NA*2) {
        int i = tid >> 1, c = tid & 1;
        out[((size_t)gidx*NA + i)*2 + c] = scl[c]*velS[tid] + mn[c];
    }
}

extern "C" void kernel_launch(void* const* d_in, const int* in_sizes, int n_in,
                              void* d_out, int out_size) {
    const float* obs  = (const float*)d_in[0];
    const float* scl  = (const float*)d_in[3];
    const float* mn   = (const float*)d_in[4];
    const float* embW = (const float*)d_in[5];
    const float* embb = (const float*)d_in[6];
    const float* We1  = (const float*)d_in[7];
    const float* be1  = (const float*)d_in[8];
    const float* We2  = (const float*)d_in[9];
    const float* be2  = (const float*)d_in[10];
    const float* Wc1  = (const float*)d_in[11];
    const float* bc1  = (const float*)d_in[12];
    const float* Wc2  = (const float*)d_in[13];
    const float* bc2  = (const float*)d_in[14];
    const float* Wv1  = (const float*)d_in[15];
    const float* bv1  = (const float*)d_in[16];
    const float* Wv2  = (const float*)d_in[17];
    const float* bv2  = (const float*)d_in[18];
    const float* Wn1  = (const float*)d_in[19];
    const float* bn1  = (const float*)d_in[20];
    const float* Wn2  = (const float*)d_in[21];
    const float* bn2  = (const float*)d_in[22];
    float* out = (float*)d_out;

    int n_nodes = in_sizes[0] / OBSW;
    int groups  = n_nodes / NA;

    cudaFuncSetAttribute(egnn_kernel, cudaFuncAttributeMaxDynamicSharedMemorySize, SMEM_BYTES);
    egnn_kernel<<<groups, NT, SMEM_BYTES>>>(
        obs, scl, mn, embW, embb,
        We1, be1, We2, be2, Wc1, bc1, Wc2, bc2,
        Wv1, bv1, Wv2, bv2, Wn1, bn1, Wn2, bn2, out);
}

// round 15
// speedup vs baseline: 1.9099x; 1.2896x over previous
#include <cuda_runtime.h>
#include <cuda_fp16.h>

#define NA    32
#define HH    64
#define HS    68      // h/A/B row stride (floats)
#define SS2   36      // slab row stride in uints (fp16 pairs); 4g+t conflict-free
#define PS    66      // paired node-weight row stride (floats)
#define NW    16
#define NPAIR 8
#define NT    512
#define NINV  16
#define NLAY  4
#define OBSW  20

// ---- smem map (float offsets) ----
#define SM_H     0
#define SM_A     (SM_H    + NA*HS)
#define SM_B     (SM_A    + NA*HS)
#define SM_MAGG  (SM_B    + NA*HS)
#define SM_EA    (SM_MAGG + NA*HH)
#define SM_W2P   (SM_EA   + NA*NA)      // We2 fp16 hi/lo plane: 1152 uint4 = 4608 floats
#define SM_WCP   (SM_W2P  + 4608)       // Wc1 plane
#define SM_SLAB  (SM_WCP  + 4608)       // 8 pair-slabs 32x36 uints = 9216 floats
#define SM_VEC   (SM_SLAB + 9216)
#define SM_LOC   (SM_VEC  + 10*HH)
#define SM_VEL   (SM_LOC  + 2*NA)
#define SM_AGG   (SM_VEL  + 2*NA)
#define SM_CS    (SM_AGG  + 2*NA)
#define SMEM_FLOATS (SM_CS + NW*NA)
#define SMEM_BYTES  (SMEM_FLOATS * 4)

// node-weight restage region = W2P..end of slab (18432 floats, contiguous)
#define NV1   (64*PS)    // 4224
#define NN1   (128*PS)   // 8448

#define V_W128 0
#define V_W129 1
#define V_BE1  2
#define V_BE2  3
#define V_BC1  4
#define V_WC2  5
#define V_BV1  6
#define V_BN1  7
#define V_BN2  8
#define V_WV2  9

#define PAIRBAR(id) asm volatile("bar.sync %0, 64;" :: "r"(id) : "memory")
#define F4C(v,i) (((const float*)&(v))[i])

typedef unsigned long long ull;

__device__ __forceinline__ float siluf(float x) {
    float hx = 0.5f * x;
    float t;
    asm("tanh.approx.f32 %0, %1;" : "=f"(t) : "f"(hx));
    return fmaf(hx, t, hx);
}

// pack two f32 -> f16x2 (lo in low half, hi in high half)
__device__ __forceinline__ unsigned pack16(float lo, float hi) {
    unsigned u;
    asm("cvt.rn.f16x2.f32 %0, %1, %2;" : "=r"(u) : "f"(hi), "f"(lo));
    return u;
}

__device__ __forceinline__ ull packf2(float x) {
    unsigned u = __float_as_uint(x);
    ull r;
    asm("mov.b64 %0, {%1, %1};" : "=l"(r) : "r"(u));
    return r;
}
__device__ __forceinline__ ull pack2(float x, float y) {
    ull r;
    asm("mov.b64 %0, {%1, %2};" : "=l"(r) : "r"(__float_as_uint(x)), "r"(__float_as_uint(y)));
    return r;
}
__device__ __forceinline__ void fma2(ull &d, ull a, ull b) {
    asm("fma.rn.f32x2 %0, %1, %2, %0;" : "+l"(d) : "l"(a), "l"(b));
}
__device__ __forceinline__ float2 unpackf2(ull v) {
    unsigned lo, hi;
    asm("mov.b64 {%0, %1}, %2;" : "=r"(lo), "=r"(hi) : "l"(v));
    return make_float2(__uint_as_float(lo), __uint_as_float(hi));
}

__device__ __forceinline__ void mma16(float (&d)[4], const unsigned (&a)[4],
                                      unsigned b0, unsigned b1) {
    asm volatile(
        "mma.sync.aligned.m16n8k16.row.col.f32.f16.f16.f32 "
        "{%0,%1,%2,%3},{%4,%5,%6,%7},{%8,%9},{%0,%1,%2,%3};"
        : "+f"(d[0]), "+f"(d[1]), "+f"(d[2]), "+f"(d[3])
        : "r"(a[0]), "r"(a[1]), "r"(a[2]), "r"(a[3]), "r"(b0), "r"(b1));
}

__device__ __forceinline__ float wredsum(float v) {
    v += __shfl_down_sync(0xffffffffu, v, 16);
    v += __shfl_down_sync(0xffffffffu, v, 8);
    v += __shfl_down_sync(0xffffffffu, v, 4);
    v += __shfl_down_sync(0xffffffffu, v, 2);
    v += __shfl_down_sync(0xffffffffu, v, 1);
    return v;
}

// Half GEMM, compensated fp16: D[32e][32n] = slab @ (Whi + Wlo) + bias.
// Slab: fp16 [edge][k], row stride SS2 uints.
// Weight plane uint4 {b0h,b0l,b1h,b1l}: WP[nt*288 + ((kt*4+t)*2+sub)*9 + g]
__device__ __forceinline__ void mma_gemm_h(const unsigned* __restrict__ slabU,
                                           const uint4* __restrict__ WP,
                                           const float* __restrict__ bias,
                                           int sub, int g, int t, float (&acc)[2][4][4])
{
    #pragma unroll
    for (int nt = 0; nt < 4; nt++) {
        float2 b = *(const float2*)(bias + nt*8 + 2*t);
        #pragma unroll
        for (int mt = 0; mt < 2; mt++) {
            acc[mt][nt][0] = b.x; acc[mt][nt][1] = b.y;
            acc[mt][nt][2] = b.x; acc[mt][nt][3] = b.y;
        }
    }
    #pragma unroll
    for (int kt = 0; kt < 4; kt++) {          // k16 chunks
        unsigned a[2][4];
        #pragma unroll
        for (int mt = 0; mt < 2; mt++) {
            const unsigned* base = slabU + (mt*16 + g)*SS2 + kt*8 + t;
            a[mt][0] = base[0];               // row g,   k 2t,2t+1
            a[mt][1] = base[8*SS2];           // row g+8, k 2t,2t+1
            a[mt][2] = base[4];               // row g,   k 2t+8,2t+9
            a[mt][3] = base[8*SS2 + 4];       // row g+8
        }
        const int widx = ((kt*4 + t)*2 + sub)*9 + g;
        #pragma unroll
        for (int nt = 0; nt < 4; nt++) {
            uint4 wv = WP[nt*288 + widx];
            mma16(acc[0][nt], a[0], wv.x, wv.z);   // hi
            mma16(acc[1][nt], a[1], wv.x, wv.z);
            mma16(acc[0][nt], a[0], wv.y, wv.w);   // lo
            mma16(acc[1][nt], a[1], wv.y, wv.w);
        }
    }
}

__global__ void __launch_bounds__(NT, 1)
egnn_kernel(const float* __restrict__ obs,
            const float* __restrict__ scl,
            const float* __restrict__ mn,
            const float* __restrict__ embW,
            const float* __restrict__ embb,
            const float* __restrict__ We1,
            const float* __restrict__ be1,
            const float* __restrict__ We2,
            const float* __restrict__ be2,
            const float* __restrict__ Wc1,
            const float* __restrict__ bc1,
            const float* __restrict__ Wc2,
            const float* __restrict__ bc2,
            const float* __restrict__ Wv1,
            const float* __restrict__ bv1,
            const float* __restrict__ Wv2,
            const float* __restrict__ bv2,
            const float* __restrict__ Wn1,
            const float* __restrict__ bn1,
            const float* __restrict__ Wn2,
            const float* __restrict__ bn2,
            float* __restrict__ out)
{
    extern __shared__ float sm[];
    float* hS    = sm + SM_H;
    float* AS    = sm + SM_A;
    float* BS    = sm + SM_B;
    float* maggS = sm + SM_MAGG;
    float* eaS   = sm + SM_EA;
    __half* W2Ph = (__half*)(sm + SM_W2P);
    __half* WCPh = (__half*)(sm + SM_WCP);
    float* slabF = sm + SM_SLAB;
    float* vecS  = sm + SM_VEC;
    float* locS  = sm + SM_LOC;
    float* velS  = sm + SM_VEL;
    float* aggS  = sm + SM_AGG;
    float* csS   = sm + SM_CS;
    float* nodeW = sm + SM_W2P;      // restage region (weights+slab, post-edge)

    float* w128s = vecS + V_W128*HH;
    float* w129s = vecS + V_W129*HH;
    float* be1s  = vecS + V_BE1*HH;
    float* be2s  = vecS + V_BE2*HH;
    float* bc1s  = vecS + V_BC1*HH;
    float* Wc2s  = vecS + V_WC2*HH;
    float* bv1s  = vecS + V_BV1*HH;
    float* bn1s  = vecS + V_BN1*HH;
    float* bn2s  = vecS + V_BN2*HH;
    float* Wv2s  = vecS + V_WV2*HH;

    const int tid  = threadIdx.x;
    const int w    = tid >> 5;
    const int lane = tid & 31;
    const int g    = lane >> 2;
    const int t    = lane & 3;
    const int pair = w >> 1;
    const int sub  = w & 1;
    const int bid  = pair + 1;
    const int gidx = blockIdx.x;

    unsigned* slabU = (unsigned*)slabF + pair * (NA*SS2);
    float* csW = csS + w * NA;

    // ---- stage obs into BS scratch ----
    const float* obsg = obs + (size_t)gidx * NA * OBSW;
    for (int q = tid; q < NA*OBSW; q += NT) BS[q] = obsg[q];
    __syncthreads();

    if (tid < NA*2) {
        int i = tid >> 1, c = tid & 1;
        locS[tid] = BS[i*OBSW + NINV + c];
        velS[tid] = BS[i*OBSW + NINV + 2 + c];
    }
    __syncthreads();

    for (int p = tid; p < NA*NA; p += NT) {
        int i = p >> 5, j = p & 31;
        float dx = locS[i*2+0] - locS[j*2+0];
        float dy = locS[i*2+1] - locS[j*2+1];
        eaS[p] = dx*dx + dy*dy;
    }

    // h = inv @ embW + embb  (warp w: rows 2w, 2w+1)
    {
        float a0[2], a1[2];
        #pragma unroll
        for (int r = 0; r < 2; r++) { a0[r] = embb[lane]; a1[r] = embb[lane+32]; }
        #pragma unroll
        for (int c = 0; c < NINV; c++) {
            float w0 = embW[c*HH + lane];
            float w1 = embW[c*HH + lane + 32];
            #pragma unroll
            for (int r = 0; r < 2; r++) {
                float iv = BS[(w*2+r)*OBSW + c];
                a0[r] += iv*w0; a1[r] += iv*w1;
            }
        }
        #pragma unroll
        for (int r = 0; r < 2; r++) {
            hS[(w*2+r)*HS + lane]      = a0[r];
            hS[(w*2+r)*HS + lane + 32] = a1[r];
        }
    }
    __syncthreads();

    #pragma unroll 1
    for (int l = 0; l < NLAY; l++) {
        // ==== stage edge weights (fp16 hi/lo fragment planes) + paired We1 + vectors ====
        {
            const float4* s2 = (const float4*)(We2 + l*HH*HH);
            const float4* sc = (const float4*)(Wc1 + l*HH*HH);
            for (int t4 = tid; t4 < 1024; t4 += NT) {
                int k  = t4 >> 4, n0 = (t4 & 15) * 4;
                int kt16 = k >> 4, kr = k & 15;
                int reg = kr >> 3, tt = (kr >> 1) & 3, hp = kr & 1;
                float4 w2 = s2[t4], wc = sc[t4];
                #pragma unroll
                for (int ii = 0; ii < 4; ii++) {
                    int n = n0 + ii;
                    int sb = n >> 5, nt = (n & 31) >> 3, g0 = n & 7;
                    int f4i = nt*288 + ((kt16*4 + tt)*2 + sb)*9 + g0;
                    int hbase = f4i*8 + reg*4 + hp;
                    float wv2 = F4C(w2, ii);
                    __half hh = __float2half_rn(wv2);
                    W2Ph[hbase]     = hh;
                    W2Ph[hbase + 2] = __float2half_rn(wv2 - __half2float(hh));
                    float wvc = F4C(wc, ii);
                    __half hc = __float2half_rn(wvc);
                    WCPh[hbase]     = hc;
                    WCPh[hbase + 2] = __float2half_rn(wvc - __half2float(hc));
                }
            }
            // We1 rows 0..127 -> paired layout into slab scratch
            const float4* We1l = (const float4*)(We1 + l*130*HH);
            for (int q = tid; q < 2048; q += NT) {
                int c = q >> 4, n0 = (q & 15) * 4;
                float4 v = We1l[q];
                float* d = slabF + (c >> 6)*NV1 + (c & 63)*PS + 2*(n0 & 31) + (n0 >> 5);
                d[0] = v.x; d[2] = v.y; d[4] = v.z; d[6] = v.w;
            }
            if (tid < HH) {
                w128s[tid] = We1[(l*130 + 128)*HH + tid];
                w129s[tid] = We1[(l*130 + 129)*HH + tid];
                be1s[tid]  = be1[l*HH + tid];
                be2s[tid]  = be2[l*HH + tid];
                bc1s[tid]  = bc1[l*HH + tid];
                Wc2s[tid]  = Wc2[l*HH + tid];
                bv1s[tid]  = bv1[l*HH + tid];
                bn1s[tid]  = bn1[l*HH + tid];
                bn2s[tid]  = bn2[l*HH + tid];
                Wv2s[tid]  = Wv2[l*HH + tid];
            }
        }
        const float bc2l = bc2[l];
        const float bv2l = bv2[l];
        __syncthreads();

        // ==== phase A (packed): A = h@We1A + be1, B = h@We1B ====
        {
            const float* We1Ap = slabF;
            const float* We1Bp = slabF + NV1;
            ull aA[2], aB[2];
            #pragma unroll
            for (int r = 0; r < 2; r++) {
                aA[r] = pack2(be1s[lane], be1s[lane + 32]);
                aB[r] = 0ull;
            }
            #pragma unroll 8
            for (int c = 0; c < HH; c++) {
                ull wpa = *(const ull*)(We1Ap + c*PS + 2*lane);
                ull wpb = *(const ull*)(We1Bp + c*PS + 2*lane);
                #pragma unroll
                for (int r = 0; r < 2; r++) {
                    ull h2 = packf2(hS[(w*2+r)*HS + c]);
                    fma2(aA[r], h2, wpa);
                    fma2(aB[r], h2, wpb);
                }
            }
            #pragma unroll
            for (int r = 0; r < 2; r++) {
                float2 fa = unpackf2(aA[r]);
                float2 fb = unpackf2(aB[r]);
                AS[(w*2+r)*HS + lane]      = fa.x;
                AS[(w*2+r)*HS + lane + 32] = fa.y;
                BS[(w*2+r)*HS + lane]      = fb.x;
                BS[(w*2+r)*HS + lane + 32] = fb.y;
            }
        }
        __syncthreads();

        // ==== edge phase: warp pair = one receiver; sub = n-half ====
        #pragma unroll 1
        for (int it = 0; it < 4; it++) {
            const int i = it*NPAIR + pair;

            // -- m1 construction (lane = sender j), this warp's channel half, fp16 --
            float dnx, dny;
            {
                const int j = lane;
                float dx = locS[i*2+0] - locS[j*2+0];
                float dy = locS[i*2+1] - locS[j*2+1];
                float rad = dx*dx + dy*dy;
                float invr = __fdividef(1.0f, sqrtf(rad) + 1.0f);
                dnx = dx * invr; dny = dy * invr;
                float eav = eaS[i*NA + j];
                const float* Ai = AS + i*HS;
                const float* Bj = BS + j*HS;
                unsigned* srow = slabU + j*SS2 + sub*16;
                #pragma unroll
                for (int c4i = 0; c4i < 8; c4i++) {
                    int c4 = sub*8 + c4i;
                    float4 wA = *(const float4*)(w128s + c4*4);
                    float4 wB = *(const float4*)(w129s + c4*4);
                    float4 a4 = *(const float4*)(Ai + c4*4);
                    float4 b4 = *(const float4*)(Bj + c4*4);
                    float v0 = siluf(a4.x + b4.x + rad*wA.x + eav*wB.x);
                    float v1 = siluf(a4.y + b4.y + rad*wA.y + eav*wB.y);
                    float v2 = siluf(a4.z + b4.z + rad*wA.z + eav*wB.z);
                    float v3 = siluf(a4.w + b4.w + rad*wA.w + eav*wB.w);
                    uint2 o = make_uint2(pack16(v0, v1), pack16(v2, v3));
                    *(uint2*)(srow + c4i*2) = o;
                }
            }
            PAIRBAR(bid);                       // m1 complete (both halves)

            float acc[2][4][4];

            // -- GEMM1 (tensor fp16): m2-half = silu(m1 @ We2 + be2) --
            mma_gemm_h(slabU, (const uint4*)W2Ph, be2s + sub*32, sub, g, t, acc);
            PAIRBAR(bid);                       // both GEMM1 reads done
            {
                float maggL[8];
                #pragma unroll
                for (int s = 0; s < 8; s++) maggL[s] = 0.f;
                float vm[2][2];
                #pragma unroll
                for (int mt = 0; mt < 2; mt++) {
                    int r0 = mt*16 + g;
                    vm[mt][0] = (r0 == i) ? 0.f : 1.f;
                    vm[mt][1] = (r0 + 8 == i) ? 0.f : 1.f;
                }
                #pragma unroll
                for (int mt = 0; mt < 2; mt++) {
                    unsigned* r0p = slabU + (mt*16 + g)*SS2 + sub*16 + 2*t;   // col base nt*4+t handled below
                    unsigned* r1p = r0p + 8*SS2;
                    #pragma unroll
                    for (int nt = 0; nt < 4; nt++) {
                        float sv0 = siluf(acc[mt][nt][0]);
                        float sv1 = siluf(acc[mt][nt][1]);
                        float sv2 = siluf(acc[mt][nt][2]);
                        float sv3 = siluf(acc[mt][nt][3]);
                        maggL[nt*2+0] = fmaf(vm[mt][0], sv0, maggL[nt*2+0]);
                        maggL[nt*2+0] = fmaf(vm[mt][1], sv2, maggL[nt*2+0]);
                        maggL[nt*2+1] = fmaf(vm[mt][0], sv1, maggL[nt*2+1]);
                        maggL[nt*2+1] = fmaf(vm[mt][1], sv3, maggL[nt*2+1]);
                        // fp16 m2 store: uint idx = row*SS2 + sub*16 + nt*4 + t
                        r0p[nt*4 - 2*t + t] = pack16(sv0, sv1);
                        r1p[nt*4 - 2*t + t] = pack16(sv2, sv3);
                    }
                }
                #pragma unroll
                for (int s = 0; s < 8; s++) {
                    maggL[s] += __shfl_xor_sync(0xffffffffu, maggL[s], 4);
                    maggL[s] += __shfl_xor_sync(0xffffffffu, maggL[s], 8);
                    maggL[s] += __shfl_xor_sync(0xffffffffu, maggL[s], 16);
                }
                if (g == 0) {
                    #pragma unroll
                    for (int nt = 0; nt < 4; nt++)
                        *(float2*)(maggS + i*HH + sub*32 + nt*8 + 2*t) =
                            make_float2(maggL[2*nt], maggL[2*nt+1]);
                }
            }
            PAIRBAR(bid);                       // m2 complete (both halves)

            // -- GEMM2 (tensor fp16): t2-half; cs partial = t2.Wc2-half --
            mma_gemm_h(slabU, (const uint4*)WCPh, bc1s + sub*32, sub, g, t, acc);
            {
                float csL[4] = {0.f, 0.f, 0.f, 0.f};
                #pragma unroll
                for (int nt = 0; nt < 4; nt++) {
                    float2 wc = *(const float2*)(Wc2s + sub*32 + nt*8 + 2*t);
                    #pragma unroll
                    for (int mt = 0; mt < 2; mt++) {
                        csL[mt*2+0] = fmaf(siluf(acc[mt][nt][0]), wc.x, csL[mt*2+0]);
                        csL[mt*2+0] = fmaf(siluf(acc[mt][nt][1]), wc.y, csL[mt*2+0]);
                        csL[mt*2+1] = fmaf(siluf(acc[mt][nt][2]), wc.x, csL[mt*2+1]);
                        csL[mt*2+1] = fmaf(siluf(acc[mt][nt][3]), wc.y, csL[mt*2+1]);
                    }
                }
                #pragma unroll
                for (int q = 0; q < 4; q++) {
                    csL[q] += __shfl_xor_sync(0xffffffffu, csL[q], 1);
                    csL[q] += __shfl_xor_sync(0xffffffffu, csL[q], 2);
                }
                if (t == 0) {
                    csW[g]      = csL[0];
                    csW[g + 8]  = csL[1];
                    csW[g + 16] = csL[2];
                    csW[g + 24] = csL[3];
                }
            }
            PAIRBAR(bid);                       // cs partials + GEMM2 reads done

            // -- combine cs halves + trans aggregation (sub 0 only) --
            if (sub == 0) {
                float cj = csS[w*NA + lane] + csS[(w+1)*NA + lane] + bc2l;
                float tx = wredsum(dnx * cj);
                float ty = wredsum(dny * cj);
                if (lane == 0) { aggS[i*2+0] = tx; aggS[i*2+1] = ty; }
            }
        }
        __syncthreads();

        // ==== restage node weights (paired layout) into weight+slab region ====
        {
            const float4* Wv1l = (const float4*)(Wv1 + l*HH*HH);
            const float4* Wn1l = (const float4*)(Wn1 + l*2*HH*HH);
            const float4* Wn2l = (const float4*)(Wn2 + l*HH*HH);
            for (int q = tid; q < 1024; q += NT) {
                int c = q >> 4, n0 = (q & 15) * 4;
                int off = c*PS + 2*(n0 & 31) + (n0 >> 5);
                float4 a = Wv1l[q];
                float* d1 = nodeW + off;
                d1[0] = a.x; d1[2] = a.y; d1[4] = a.z; d1[6] = a.w;
                float4 b = Wn2l[q];
                float* d3 = nodeW + NV1 + NN1 + off;
                d3[0] = b.x; d3[2] = b.y; d3[4] = b.z; d3[6] = b.w;
            }
            for (int q = tid; q < 2048; q += NT) {
                int c = q >> 4, n0 = (q & 15) * 4;
                float4 a = Wn1l[q];
                float* d2 = nodeW + NV1 + c*PS + 2*(n0 & 31) + (n0 >> 5);
                d2[0] = a.x; d2[2] = a.y; d2[4] = a.z; d2[6] = a.w;
            }
        }
        __syncthreads();
        const float* Wv1p = nodeW;
        const float* Wn1p = nodeW + NV1;
        const float* Wn2p = nodeW + NV1 + NN1;

        // ==== node phase (packed): phi_v, vel/loc update ====
        {
            ull acc2[2];
            #pragma unroll
            for (int r = 0; r < 2; r++) acc2[r] = pack2(bv1s[lane], bv1s[lane+32]);
            #pragma unroll 8
            for (int c = 0; c < HH; c++) {
                ull wp = *(const ull*)(Wv1p + c*PS + 2*lane);
                #pragma unroll
                for (int r = 0; r < 2; r++)
                    fma2(acc2[r], packf2(hS[(w*2+r)*HS + c]), wp);
            }
            float wv2a = Wv2s[lane], wv2b = Wv2s[lane + 32];
            #pragma unroll
            for (int r = 0; r < 2; r++) {
                float2 f = unpackf2(acc2[r]);
                float part = wredsum(siluf(f.x)*wv2a + siluf(f.y)*wv2b);
                if (lane == 0) {
                    int i = w*2 + r;
                    float phi = part + bv2l;
                    float vx = phi*velS[i*2+0] + aggS[i*2+0]*(1.0f/31.0f);
                    float vy = phi*velS[i*2+1] + aggS[i*2+1]*(1.0f/31.0f);
                    velS[i*2+0] = vx; velS[i*2+1] = vy;
                    locS[i*2+0] += vx; locS[i*2+1] += vy;
                }
            }
        }

        // ==== U = silu([h, magg] @ Wn1 + bn1) -> AS (packed) ====
        {
            ull acc2[2];
            #pragma unroll
            for (int r = 0; r < 2; r++) acc2[r] = pack2(bn1s[lane], bn1s[lane+32]);
            #pragma unroll 8
            for (int c = 0; c < HH; c++) {
                ull wp = *(const ull*)(Wn1p + c*PS + 2*lane);
                #pragma unroll
                for (int r = 0; r < 2; r++)
                    fma2(acc2[r], packf2(hS[(w*2+r)*HS + c]), wp);
            }
            #pragma unroll 8
            for (int c = 0; c < HH; c++) {
                ull wp = *(const ull*)(Wn1p + (HH + c)*PS + 2*lane);
                #pragma unroll
                for (int r = 0; r < 2; r++)
                    fma2(acc2[r], packf2(maggS[(w*2+r)*HH + c]), wp);
            }
            #pragma unroll
            for (int r = 0; r < 2; r++) {
                float2 f = unpackf2(acc2[r]);
                AS[(w*2+r)*HS + lane]      = siluf(f.x);
                AS[(w*2+r)*HS + lane + 32] = siluf(f.y);
            }
        }

        // ==== h += U @ Wn2 + bn2 (packed) ====
        {
            ull acc2[2];
            #pragma unroll
            for (int r = 0; r < 2; r++) acc2[r] = pack2(bn2s[lane], bn2s[lane+32]);
            #pragma unroll 8
            for (int c = 0; c < HH; c++) {
                ull wp = *(const ull*)(Wn2p + c*PS + 2*lane);
                #pragma unroll
                for (int r = 0; r < 2; r++)
                    fma2(acc2[r], packf2(AS[(w*2+r)*HS + c]), wp);
            }
            #pragma unroll
            for (int r = 0; r < 2; r++) {
                float2 f = unpackf2(acc2[r]);
                hS[(w*2+r)*HS + lane]      += f.x;
                hS[(w*2+r)*HS + lane + 32] += f.y;
            }
        }
        __syncthreads();
    }

    // ---- output ----
    if (tid < NA*2) {
        int i = tid >> 1, c = tid & 1;
        out[((size_t)gidx*NA + i)*2 + c] = scl[c]*velS[tid] + mn[c];
    }
}

extern "C" void kernel_launch(void* const* d_in, const int* in_sizes, int n_in,
                              void* d_out, int out_size) {
    const float* obs  = (const float*)d_in[0];
    const float* scl  = (const float*)d_in[3];
    const float* mn   = (const float*)d_in[4];
    const float* embW = (const float*)d_in[5];
    const float* embb = (const float*)d_in[6];
    const float* We1  = (const float*)d_in[7];
    const float* be1  = (const float*)d_in[8];
    const float* We2  = (const float*)d_in[9];
    const float* be2  = (const float*)d_in[10];
    const float* Wc1  = (const float*)d_in[11];
    const float* bc1  = (const float*)d_in[12];
    const float* Wc2  = (const float*)d_in[13];
    const float* bc2  = (const float*)d_in[14];
    const float* Wv1  = (const float*)d_in[15];
    const float* bv1  = (const float*)d_in[16];
    const float* Wv2  = (const float*)d_in[17];
    const float* bv2  = (const float*)d_in[18];
    const float* Wn1  = (const float*)d_in[19];
    const float* bn1  = (const float*)d_in[20];
    const float* Wn2  = (const float*)d_in[21];
    const float* bn2  = (const float*)d_in[22];
    float* out = (float*)d_out;

    int n_nodes = in_sizes[0] / OBSW;
    int groups  = n_nodes / NA;

    cudaFuncSetAttribute(egnn_kernel, cudaFuncAttributeMaxDynamicSharedMemorySize, SMEM_BYTES);
    egnn_kernel<<<groups, NT, SMEM_BYTES>>>(
        obs, scl, mn, embW, embb,
        We1, be1, We2, be2, Wc1, bc1, Wc2, bc2,
        Wv1, bv1, Wv2, bv2, Wn1, bn1, Wn2, bn2, out);
}

// round 16
// speedup vs baseline: 1.9899x; 1.0419x over previous
#include <cuda_runtime.h>
#include <cuda_fp16.h>

#define NA    32
#define HH    64
#define HS    68      // h/A/B row stride (floats)
#define SS2   36      // slab row stride in uints (fp16 pairs)
#define PS    66      // paired node-weight row stride (floats)
#define NW    8
#define NPAIR 4
#define NT    256
#define NINV  16
#define NLAY  4
#define OBSW  20

// ---- smem map (float offsets) ----
#define SM_H     0
#define SM_A     (SM_H    + NA*HS)
#define SM_B     (SM_A    + NA*HS)
#define SM_MAGG  (SM_B    + NA*HS)
#define SM_EA    (SM_MAGG + NA*HH)
#define SM_W2P   (SM_EA   + NA*NA)      // We2 fp16 hi/lo plane (4608 floats)
#define SM_WCP   (SM_W2P  + 4608)       // Wc1 plane
#define SM_SLAB  (SM_WCP  + 4608)       // 4 pair-slabs 64x36 uints = 9216 floats
#define SM_VEC   (SM_SLAB + 9216)
#define SM_LOC   (SM_VEC  + 10*HH)
#define SM_VEL   (SM_LOC  + 2*NA)
#define SM_AGG   (SM_VEL  + 2*NA)
#define SM_CS    (SM_AGG  + 2*NA)       // 8 warps x 64 partials
#define SMEM_FLOATS (SM_CS + NW*64)
#define SMEM_BYTES  (SMEM_FLOATS * 4)

#define NV1   (64*PS)
#define NN1   (128*PS)

#define V_W128 0
#define V_W129 1
#define V_BE1  2
#define V_BE2  3
#define V_BC1  4
#define V_WC2  5
#define V_BV1  6
#define V_BN1  7
#define V_BN2  8
#define V_WV2  9

#define PAIRBAR(id) asm volatile("bar.sync %0, 64;" :: "r"(id) : "memory")
#define F4C(v,i) (((const float*)&(v))[i])

typedef unsigned long long ull;

__device__ __forceinline__ float siluf(float x) {
    float hx = 0.5f * x;
    float t;
    asm("tanh.approx.f32 %0, %1;" : "=f"(t) : "f"(hx));
    return fmaf(hx, t, hx);
}

__device__ __forceinline__ unsigned pack16(float lo, float hi) {
    unsigned u;
    asm("cvt.rn.f16x2.f32 %0, %1, %2;" : "=r"(u) : "f"(hi), "f"(lo));
    return u;
}

__device__ __forceinline__ ull packf2(float x) {
    unsigned u = __float_as_uint(x);
    ull r;
    asm("mov.b64 %0, {%1, %1};" : "=l"(r) : "r"(u));
    return r;
}
__device__ __forceinline__ ull pack2(float x, float y) {
    ull r;
    asm("mov.b64 %0, {%1, %2};" : "=l"(r) : "r"(__float_as_uint(x)), "r"(__float_as_uint(y)));
    return r;
}
__device__ __forceinline__ void fma2(ull &d, ull a, ull b) {
    asm("fma.rn.f32x2 %0, %1, %2, %0;" : "+l"(d) : "l"(a), "l"(b));
}
__device__ __forceinline__ float2 unpackf2(ull v) {
    unsigned lo, hi;
    asm("mov.b64 {%0, %1}, %2;" : "=r"(lo), "=r"(hi) : "l"(v));
    return make_float2(__uint_as_float(lo), __uint_as_float(hi));
}

__device__ __forceinline__ void mma16(float (&d)[4], const unsigned (&a)[4],
                                      unsigned b0, unsigned b1) {
    asm volatile(
        "mma.sync.aligned.m16n8k16.row.col.f32.f16.f16.f32 "
        "{%0,%1,%2,%3},{%4,%5,%6,%7},{%8,%9},{%0,%1,%2,%3};"
        : "+f"(d[0]), "+f"(d[1]), "+f"(d[2]), "+f"(d[3])
        : "r"(a[0]), "r"(a[1]), "r"(a[2]), "r"(a[3]), "r"(b0), "r"(b1));
}

__device__ __forceinline__ float wredsum(float v) {
    v += __shfl_down_sync(0xffffffffu, v, 16);
    v += __shfl_down_sync(0xffffffffu, v, 8);
    v += __shfl_down_sync(0xffffffffu, v, 4);
    v += __shfl_down_sync(0xffffffffu, v, 2);
    v += __shfl_down_sync(0xffffffffu, v, 1);
    return v;
}

// Half GEMM, M=64 (2 receivers), compensated fp16.
// Slab: fp16 [64 rows][64 k], row stride SS2 uints (rows 0..31 recv0, 32..63 recv1).
// Weight plane uint4 {b0h,b0l,b1h,b1l}: WP[nt*288 + ((kt*4+t)*2+sub)*9 + g]
__device__ __forceinline__ void mma_gemm_h(const unsigned* __restrict__ slabU,
                                           const uint4* __restrict__ WP,
                                           const float* __restrict__ bias,
                                           int sub, int g, int t, float (&acc)[4][4][4])
{
    #pragma unroll
    for (int nt = 0; nt < 4; nt++) {
        float2 b = *(const float2*)(bias + nt*8 + 2*t);
        #pragma unroll
        for (int mt = 0; mt < 4; mt++) {
            acc[mt][nt][0] = b.x; acc[mt][nt][1] = b.y;
            acc[mt][nt][2] = b.x; acc[mt][nt][3] = b.y;
        }
    }
    #pragma unroll
    for (int kt = 0; kt < 4; kt++) {
        unsigned a[4][4];
        #pragma unroll
        for (int mt = 0; mt < 4; mt++) {
            const unsigned* base = slabU + (mt*16 + g)*SS2 + kt*8 + t;
            a[mt][0] = base[0];
            a[mt][1] = base[8*SS2];
            a[mt][2] = base[4];
            a[mt][3] = base[8*SS2 + 4];
        }
        const int widx = ((kt*4 + t)*2 + sub)*9 + g;
        #pragma unroll
        for (int nt = 0; nt < 4; nt++) {
            uint4 wv = WP[nt*288 + widx];
            #pragma unroll
            for (int mt = 0; mt < 4; mt++) mma16(acc[mt][nt], a[mt], wv.x, wv.z);
            #pragma unroll
            for (int mt = 0; mt < 4; mt++) mma16(acc[mt][nt], a[mt], wv.y, wv.w);
        }
    }
}

__global__ void __launch_bounds__(NT, 1)
egnn_kernel(const float* __restrict__ obs,
            const float* __restrict__ scl,
            const float* __restrict__ mn,
            const float* __restrict__ embW,
            const float* __restrict__ embb,
            const float* __restrict__ We1,
            const float* __restrict__ be1,
            const float* __restrict__ We2,
            const float* __restrict__ be2,
            const float* __restrict__ Wc1,
            const float* __restrict__ bc1,
            const float* __restrict__ Wc2,
            const float* __restrict__ bc2,
            const float* __restrict__ Wv1,
            const float* __restrict__ bv1,
            const float* __restrict__ Wv2,
            const float* __restrict__ bv2,
            const float* __restrict__ Wn1,
            const float* __restrict__ bn1,
            const float* __restrict__ Wn2,
            const float* __restrict__ bn2,
            float* __restrict__ out)
{
    extern __shared__ float sm[];
    float* hS    = sm + SM_H;
    float* AS    = sm + SM_A;
    float* BS    = sm + SM_B;
    float* maggS = sm + SM_MAGG;
    float* eaS   = sm + SM_EA;
    __half* W2Ph = (__half*)(sm + SM_W2P);
    __half* WCPh = (__half*)(sm + SM_WCP);
    float* slabF = sm + SM_SLAB;
    float* vecS  = sm + SM_VEC;
    float* locS  = sm + SM_LOC;
    float* velS  = sm + SM_VEL;
    float* aggS  = sm + SM_AGG;
    float* csS   = sm + SM_CS;
    float* nodeW = sm + SM_W2P;      // restage region (weights+slab, post-edge)

    float* w128s = vecS + V_W128*HH;
    float* w129s = vecS + V_W129*HH;
    float* be1s  = vecS + V_BE1*HH;
    float* be2s  = vecS + V_BE2*HH;
    float* bc1s  = vecS + V_BC1*HH;
    float* Wc2s  = vecS + V_WC2*HH;
    float* bv1s  = vecS + V_BV1*HH;
    float* bn1s  = vecS + V_BN1*HH;
    float* bn2s  = vecS + V_BN2*HH;
    float* Wv2s  = vecS + V_WV2*HH;

    const int tid  = threadIdx.x;
    const int w    = tid >> 5;         // 0..7
    const int lane = tid & 31;
    const int g    = lane >> 2;
    const int t    = lane & 3;
    const int pair = w >> 1;           // 0..3
    const int sub  = w & 1;
    const int bid  = pair + 1;
    const int gidx = blockIdx.x;

    unsigned* slabU = (unsigned*)slabF + pair * (64*SS2);
    float* csW = csS + w * 64;

    // ---- stage obs into BS scratch ----
    const float* obsg = obs + (size_t)gidx * NA * OBSW;
    for (int q = tid; q < NA*OBSW; q += NT) BS[q] = obsg[q];
    __syncthreads();

    if (tid < NA*2) {
        int i = tid >> 1, c = tid & 1;
        locS[tid] = BS[i*OBSW + NINV + c];
        velS[tid] = BS[i*OBSW + NINV + 2 + c];
    }
    __syncthreads();

    for (int p = tid; p < NA*NA; p += NT) {
        int i = p >> 5, j = p & 31;
        float dx = locS[i*2+0] - locS[j*2+0];
        float dy = locS[i*2+1] - locS[j*2+1];
        eaS[p] = dx*dx + dy*dy;
    }

    // h = inv @ embW + embb  (warp w: rows 4w..4w+3)
    {
        float a0[4], a1[4];
        #pragma unroll
        for (int r = 0; r < 4; r++) { a0[r] = embb[lane]; a1[r] = embb[lane+32]; }
        #pragma unroll
        for (int c = 0; c < NINV; c++) {
            float w0 = embW[c*HH + lane];
            float w1 = embW[c*HH + lane + 32];
            #pragma unroll
            for (int r = 0; r < 4; r++) {
                float iv = BS[(w*4+r)*OBSW + c];
                a0[r] += iv*w0; a1[r] += iv*w1;
            }
        }
        #pragma unroll
        for (int r = 0; r < 4; r++) {
            hS[(w*4+r)*HS + lane]      = a0[r];
            hS[(w*4+r)*HS + lane + 32] = a1[r];
        }
    }
    __syncthreads();

    #pragma unroll 1
    for (int l = 0; l < NLAY; l++) {
        // ==== stage edge weights (fp16 hi/lo fragment planes) + paired We1 + vectors ====
        {
            const float4* s2 = (const float4*)(We2 + l*HH*HH);
            const float4* sc = (const float4*)(Wc1 + l*HH*HH);
            for (int t4 = tid; t4 < 1024; t4 += NT) {
                int k  = t4 >> 4, n0 = (t4 & 15) * 4;
                int kt16 = k >> 4, kr = k & 15;
                int reg = kr >> 3, tt = (kr >> 1) & 3, hp = kr & 1;
                float4 w2 = s2[t4], wc = sc[t4];
                #pragma unroll
                for (int ii = 0; ii < 4; ii++) {
                    int n = n0 + ii;
                    int sb = n >> 5, nt = (n & 31) >> 3, g0 = n & 7;
                    int f4i = nt*288 + ((kt16*4 + tt)*2 + sb)*9 + g0;
                    int hbase = f4i*8 + reg*4 + hp;
                    float wv2 = F4C(w2, ii);
                    __half hh = __float2half_rn(wv2);
                    W2Ph[hbase]     = hh;
                    W2Ph[hbase + 2] = __float2half_rn(wv2 - __half2float(hh));
                    float wvc = F4C(wc, ii);
                    __half hc = __float2half_rn(wvc);
                    WCPh[hbase]     = hc;
                    WCPh[hbase + 2] = __float2half_rn(wvc - __half2float(hc));
                }
            }
            const float4* We1l = (const float4*)(We1 + l*130*HH);
            for (int q = tid; q < 2048; q += NT) {
                int c = q >> 4, n0 = (q & 15) * 4;
                float4 v = We1l[q];
                float* d = slabF + (c >> 6)*NV1 + (c & 63)*PS + 2*(n0 & 31) + (n0 >> 5);
                d[0] = v.x; d[2] = v.y; d[4] = v.z; d[6] = v.w;
            }
            if (tid < HH) {
                w128s[tid] = We1[(l*130 + 128)*HH + tid];
                w129s[tid] = We1[(l*130 + 129)*HH + tid];
                be1s[tid]  = be1[l*HH + tid];
                be2s[tid]  = be2[l*HH + tid];
                bc1s[tid]  = bc1[l*HH + tid];
                Wc2s[tid]  = Wc2[l*HH + tid];
                bv1s[tid]  = bv1[l*HH + tid];
                bn1s[tid]  = bn1[l*HH + tid];
                bn2s[tid]  = bn2[l*HH + tid];
                Wv2s[tid]  = Wv2[l*HH + tid];
            }
        }
        const float bc2l = bc2[l];
        const float bv2l = bv2[l];
        __syncthreads();

        // ==== phase A (packed): A = h@We1A + be1, B = h@We1B (rows 4w..4w+3) ====
        {
            const float* We1Ap = slabF;
            const float* We1Bp = slabF + NV1;
            ull aA[4], aB[4];
            #pragma unroll
            for (int r = 0; r < 4; r++) {
                aA[r] = pack2(be1s[lane], be1s[lane + 32]);
                aB[r] = 0ull;
            }
            #pragma unroll 8
            for (int c = 0; c < HH; c++) {
                ull wpa = *(const ull*)(We1Ap + c*PS + 2*lane);
                ull wpb = *(const ull*)(We1Bp + c*PS + 2*lane);
                #pragma unroll
                for (int r = 0; r < 4; r++) {
                    ull h2 = packf2(hS[(w*4+r)*HS + c]);
                    fma2(aA[r], h2, wpa);
                    fma2(aB[r], h2, wpb);
                }
            }
            #pragma unroll
            for (int r = 0; r < 4; r++) {
                float2 fa = unpackf2(aA[r]);
                float2 fb = unpackf2(aB[r]);
                AS[(w*4+r)*HS + lane]      = fa.x;
                AS[(w*4+r)*HS + lane + 32] = fa.y;
                BS[(w*4+r)*HS + lane]      = fb.x;
                BS[(w*4+r)*HS + lane + 32] = fb.y;
            }
        }
        __syncthreads();

        // ==== edge phase: pair = 2 receivers per iteration; sub = n-half ====
        #pragma unroll 1
        for (int it = 0; it < 4; it++) {
            const int iA = it*8 + pair;        // receiver 0 (slab rows 0..31)
            const int iB = it*8 + 4 + pair;    // receiver 1 (slab rows 32..63)

            // -- m1 construction (lane = sender j, both receivers) --
            float dnx[2], dny[2];
            {
                const int j = lane;
                float lx = locS[j*2+0], ly = locS[j*2+1];
                float rad[2], eav[2];
                const int iR[2] = {iA, iB};
                #pragma unroll
                for (int r = 0; r < 2; r++) {
                    float dx = locS[iR[r]*2+0] - lx;
                    float dy = locS[iR[r]*2+1] - ly;
                    rad[r] = dx*dx + dy*dy;
                    float invr = __fdividef(1.0f, sqrtf(rad[r]) + 1.0f);
                    dnx[r] = dx * invr; dny[r] = dy * invr;
                    eav[r] = eaS[iR[r]*NA + j];
                }
                const float* Bj  = BS + j*HS;
                const float* Ai0 = AS + iA*HS;
                const float* Ai1 = AS + iB*HS;
                unsigned* srow0 = slabU + j*SS2 + sub*16;
                unsigned* srow1 = srow0 + 32*SS2;
                #pragma unroll
                for (int c4i = 0; c4i < 8; c4i++) {
                    int c4 = sub*8 + c4i;
                    float4 wA = *(const float4*)(w128s + c4*4);
                    float4 wB = *(const float4*)(w129s + c4*4);
                    float4 b4 = *(const float4*)(Bj + c4*4);
                    float4 a0 = *(const float4*)(Ai0 + c4*4);
                    float4 a1 = *(const float4*)(Ai1 + c4*4);
                    float u0 = siluf(a0.x + b4.x + rad[0]*wA.x + eav[0]*wB.x);
                    float u1 = siluf(a0.y + b4.y + rad[0]*wA.y + eav[0]*wB.y);
                    float u2 = siluf(a0.z + b4.z + rad[0]*wA.z + eav[0]*wB.z);
                    float u3 = siluf(a0.w + b4.w + rad[0]*wA.w + eav[0]*wB.w);
                    *(uint2*)(srow0 + c4i*2) = make_uint2(pack16(u0,u1), pack16(u2,u3));
                    float v0 = siluf(a1.x + b4.x + rad[1]*wA.x + eav[1]*wB.x);
                    float v1 = siluf(a1.y + b4.y + rad[1]*wA.y + eav[1]*wB.y);
                    float v2 = siluf(a1.z + b4.z + rad[1]*wA.z + eav[1]*wB.z);
                    float v3 = siluf(a1.w + b4.w + rad[1]*wA.w + eav[1]*wB.w);
                    *(uint2*)(srow1 + c4i*2) = make_uint2(pack16(v0,v1), pack16(v2,v3));
                }
            }
            PAIRBAR(bid);                       // m1 complete (both halves)

            float acc[4][4][4];

            // -- GEMM1 (tensor fp16, M=64): m2-half = silu(m1 @ We2 + be2) --
            mma_gemm_h(slabU, (const uint4*)W2Ph, be2s + sub*32, sub, g, t, acc);
            PAIRBAR(bid);                       // both GEMM1 reads done
            {
                float maggL[2][8];
                #pragma unroll
                for (int rr = 0; rr < 2; rr++)
                    #pragma unroll
                    for (int s = 0; s < 8; s++) maggL[rr][s] = 0.f;
                #pragma unroll
                for (int mt = 0; mt < 4; mt++) {
                    const int rcv = mt >> 1;
                    const int iR  = rcv ? iB : iA;
                    const int j0  = (mt & 1)*16 + g;
                    const float vm0 = (j0     == iR) ? 0.f : 1.f;
                    const float vm1 = (j0 + 8 == iR) ? 0.f : 1.f;
                    unsigned* r0p = slabU + (mt*16 + g)*SS2 + sub*16 + t;
                    unsigned* r1p = r0p + 8*SS2;
                    #pragma unroll
                    for (int nt = 0; nt < 4; nt++) {
                        float sv0 = siluf(acc[mt][nt][0]);
                        float sv1 = siluf(acc[mt][nt][1]);
                        float sv2 = siluf(acc[mt][nt][2]);
                        float sv3 = siluf(acc[mt][nt][3]);
                        maggL[rcv][nt*2+0] = fmaf(vm0, sv0, maggL[rcv][nt*2+0]);
                        maggL[rcv][nt*2+0] = fmaf(vm1, sv2, maggL[rcv][nt*2+0]);
                        maggL[rcv][nt*2+1] = fmaf(vm0, sv1, maggL[rcv][nt*2+1]);
                        maggL[rcv][nt*2+1] = fmaf(vm1, sv3, maggL[rcv][nt*2+1]);
                        r0p[nt*4] = pack16(sv0, sv1);
                        r1p[nt*4] = pack16(sv2, sv3);
                    }
                }
                #pragma unroll
                for (int rr = 0; rr < 2; rr++)
                    #pragma unroll
                    for (int s = 0; s < 8; s++) {
                        maggL[rr][s] += __shfl_xor_sync(0xffffffffu, maggL[rr][s], 4);
                        maggL[rr][s] += __shfl_xor_sync(0xffffffffu, maggL[rr][s], 8);
                        maggL[rr][s] += __shfl_xor_sync(0xffffffffu, maggL[rr][s], 16);
                    }
                if (g == 0) {
                    #pragma unroll
                    for (int nt = 0; nt < 4; nt++) {
                        *(float2*)(maggS + iA*HH + sub*32 + nt*8 + 2*t) =
                            make_float2(maggL[0][2*nt], maggL[0][2*nt+1]);
                        *(float2*)(maggS + iB*HH + sub*32 + nt*8 + 2*t) =
                            make_float2(maggL[1][2*nt], maggL[1][2*nt+1]);
                    }
                }
            }
            PAIRBAR(bid);                       // m2 complete (both halves)

            // -- GEMM2 (tensor fp16, M=64): t2-half; cs partial = t2.Wc2-half --
            mma_gemm_h(slabU, (const uint4*)WCPh, bc1s + sub*32, sub, g, t, acc);
            {
                float csL[8];
                #pragma unroll
                for (int q = 0; q < 8; q++) csL[q] = 0.f;
                #pragma unroll
                for (int nt = 0; nt < 4; nt++) {
                    float2 wc = *(const float2*)(Wc2s + sub*32 + nt*8 + 2*t);
                    #pragma unroll
                    for (int mt = 0; mt < 4; mt++) {
                        csL[mt*2+0] = fmaf(siluf(acc[mt][nt][0]), wc.x, csL[mt*2+0]);
                        csL[mt*2+0] = fmaf(siluf(acc[mt][nt][1]), wc.y, csL[mt*2+0]);
                        csL[mt*2+1] = fmaf(siluf(acc[mt][nt][2]), wc.x, csL[mt*2+1]);
                        csL[mt*2+1] = fmaf(siluf(acc[mt][nt][3]), wc.y, csL[mt*2+1]);
                    }
                }
                #pragma unroll
                for (int q = 0; q < 8; q++) {
                    csL[q] += __shfl_xor_sync(0xffffffffu, csL[q], 1);
                    csL[q] += __shfl_xor_sync(0xffffffffu, csL[q], 2);
                }
                if (t == 0) {
                    #pragma unroll
                    for (int mt = 0; mt < 4; mt++) {
                        int base = (mt >> 1)*32 + (mt & 1)*16 + g;
                        csW[base]     = csL[mt*2+0];
                        csW[base + 8] = csL[mt*2+1];
                    }
                }
            }
            PAIRBAR(bid);                       // cs partials + GEMM2 reads done

            // -- combine cs halves + trans aggregation (sub 0 only) --
            if (sub == 0) {
                const int iR[2] = {iA, iB};
                #pragma unroll
                for (int r = 0; r < 2; r++) {
                    float cj = csS[w*64 + r*32 + lane]
                             + csS[(w+1)*64 + r*32 + lane] + bc2l;
                    float tx = wredsum(dnx[r] * cj);
                    float ty = wredsum(dny[r] * cj);
                    if (lane == 0) { aggS[iR[r]*2+0] = tx; aggS[iR[r]*2+1] = ty; }
                }
            }
        }
        __syncthreads();

        // ==== restage node weights (paired layout) into weight+slab region ====
        {
            const float4* Wv1l = (const float4*)(Wv1 + l*HH*HH);
            const float4* Wn1l = (const float4*)(Wn1 + l*2*HH*HH);
            const float4* Wn2l = (const float4*)(Wn2 + l*HH*HH);
            for (int q = tid; q < 1024; q += NT) {
                int c = q >> 4, n0 = (q & 15) * 4;
                int off = c*PS + 2*(n0 & 31) + (n0 >> 5);
                float4 a = Wv1l[q];
                float* d1 = nodeW + off;
                d1[0] = a.x; d1[2] = a.y; d1[4] = a.z; d1[6] = a.w;
                float4 b = Wn2l[q];
                float* d3 = nodeW + NV1 + NN1 + off;
                d3[0] = b.x; d3[2] = b.y; d3[4] = b.z; d3[6] = b.w;
            }
            for (int q = tid; q < 2048; q += NT) {
                int c = q >> 4, n0 = (q & 15) * 4;
                float4 a = Wn1l[q];
                float* d2 = nodeW + NV1 + c*PS + 2*(n0 & 31) + (n0 >> 5);
                d2[0] = a.x; d2[2] = a.y; d2[4] = a.z; d2[6] = a.w;
            }
        }
        __syncthreads();
        const float* Wv1p = nodeW;
        const float* Wn1p = nodeW + NV1;
        const float* Wn2p = nodeW + NV1 + NN1;

        // ==== node phase (packed): phi_v, vel/loc update (rows 4w..4w+3) ====
        {
            ull acc2[4];
            #pragma unroll
            for (int r = 0; r < 4; r++) acc2[r] = pack2(bv1s[lane], bv1s[lane+32]);
            #pragma unroll 8
            for (int c = 0; c < HH; c++) {
                ull wp = *(const ull*)(Wv1p + c*PS + 2*lane);
                #pragma unroll
                for (int r = 0; r < 4; r++)
                    fma2(acc2[r], packf2(hS[(w*4+r)*HS + c]), wp);
            }
            float wv2a = Wv2s[lane], wv2b = Wv2s[lane + 32];
            #pragma unroll
            for (int r = 0; r < 4; r++) {
                float2 f = unpackf2(acc2[r]);
                float part = wredsum(siluf(f.x)*wv2a + siluf(f.y)*wv2b);
                if (lane == 0) {
                    int i = w*4 + r;
                    float phi = part + bv2l;
                    float vx = phi*velS[i*2+0] + aggS[i*2+0]*(1.0f/31.0f);
                    float vy = phi*velS[i*2+1] + aggS[i*2+1]*(1.0f/31.0f);
                    velS[i*2+0] = vx; velS[i*2+1] = vy;
                    locS[i*2+0] += vx; locS[i*2+1] += vy;
                }
            }
        }

        // ==== U = silu([h, magg] @ Wn1 + bn1) -> AS (packed) ====
        {
            ull acc2[4];
            #pragma unroll
            for (int r = 0; r < 4; r++) acc2[r] = pack2(bn1s[lane], bn1s[lane+32]);
            #pragma unroll 8
            for (int c = 0; c < HH; c++) {
                ull wp = *(const ull*)(Wn1p + c*PS + 2*lane);
                #pragma unroll
                for (int r = 0; r < 4; r++)
                    fma2(acc2[r], packf2(hS[(w*4+r)*HS + c]), wp);
            }
            #pragma unroll 8
            for (int c = 0; c < HH; c++) {
                ull wp = *(const ull*)(Wn1p + (HH + c)*PS + 2*lane);
                #pragma unroll
                for (int r = 0; r < 4; r++)
                    fma2(acc2[r], packf2(maggS[(w*4+r)*HH + c]), wp);
            }
            #pragma unroll
            for (int r = 0; r < 4; r++) {
                float2 f = unpackf2(acc2[r]);
                AS[(w*4+r)*HS + lane]      = siluf(f.x);
                AS[(w*4+r)*HS + lane + 32] = siluf(f.y);
            }
        }

        // ==== h += U @ Wn2 + bn2 (packed) ====
        {
            ull acc2[4];
            #pragma unroll
            for (int r = 0; r < 4; r++) acc2[r] = pack2(bn2s[lane], bn2s[lane+32]);
            #pragma unroll 8
            for (int c = 0; c < HH; c++) {
                ull wp = *(const ull*)(Wn2p + c*PS + 2*lane);
                #pragma unroll
                for (int r = 0; r < 4; r++)
                    fma2(acc2[r], packf2(AS[(w*4+r)*HS + c]), wp);
            }
            #pragma unroll
            for (int r = 0; r < 4; r++) {
                float2 f = unpackf2(acc2[r]);
                hS[(w*4+r)*HS + lane]      += f.x;
                hS[(w*4+r)*HS + lane + 32] += f.y;
            }
        }
        __syncthreads();
    }

    // ---- output ----
    if (tid < NA*2) {
        int i = tid >> 1, c = tid & 1;
        out[((size_t)gidx*NA + i)*2 + c] = scl[c]*velS[tid] + mn[c];
    }
}

extern "C" void kernel_launch(void* const* d_in, const int* in_sizes, int n_in,
                              void* d_out, int out_size) {
    const float* obs  = (const float*)d_in[0];
    const float* scl  = (const float*)d_in[3];
    const float* mn   = (const float*)d_in[4];
    const float* embW = (const float*)d_in[5];
    const float* embb = (const float*)d_in[6];
    const float* We1  = (const float*)d_in[7];
    const float* be1  = (const float*)d_in[8];
    const float* We2  = (const float*)d_in[9];
    const float* be2  = (const float*)d_in[10];
    const float* Wc1  = (const float*)d_in[11];
    const float* bc1  = (const float*)d_in[12];
    const float* Wc2  = (const float*)d_in[13];
    const float* bc2  = (const float*)d_in[14];
    const float* Wv1  = (const float*)d_in[15];
    const float* bv1  = (const float*)d_in[16];
    const float* Wv2  = (const float*)d_in[17];
    const float* bv2  = (const float*)d_in[18];
    const float* Wn1  = (const float*)d_in[19];
    const float* bn1  = (const float*)d_in[20];
    const float* Wn2  = (const float*)d_in[21];
    const float* bn2  = (const float*)d_in[22];
    float* out = (float*)d_out;

    int n_nodes = in_sizes[0] / OBSW;
    int groups  = n_nodes / NA;

    cudaFuncSetAttribute(egnn_kernel, cudaFuncAttributeMaxDynamicSharedMemorySize, SMEM_BYTES);
    egnn_kernel<<<groups, NT, SMEM_BYTES>>>(
        obs, scl, mn, embW, embb,
        We1, be1, We2, be2, Wc1, bc1, Wc2, bc2,
        Wv1, bv1, Wv2, bv2, Wn1, bn1, Wn2, bn2, out);
}